// round 1
// baseline (speedup 1.0000x reference)
#include <cuda_runtime.h>
#include <math.h>
#include <stdint.h>

#define BATCH 16384
#define TT 32
#define DD 64
#define SS 16
#define NROWS_B (BATCH*TT)   // 524288
#define NROWS_0 (BATCH*SS)   // 262144

// ---------------- scratch (device globals; no allocations allowed) -------------
__device__ float g_beta[(size_t)NROWS_B*128];   // beta_{b,t} (128)
__device__ float g_qkvb[(size_t)NROWS_B*384];   // clin(beta): q(128)|k(128)|v(128)
__device__ float g_qkv0[(size_t)NROWS_0*384];   // clin(mem0)
__device__ float g_alpha[NROWS_B];
__device__ float g_ptrs[(size_t)NROWS_B*16];
__device__ float g_Wc[128*384];
__device__ int   g_active;

// ---------------- build combined weight: [128 x 384] ---------------------------
__global__ void build_wc_kernel(const float* __restrict__ Wqr, const float* __restrict__ Wqi,
                                const float* __restrict__ Wkr, const float* __restrict__ Wki,
                                const float* __restrict__ Wvr, const float* __restrict__ Wvi) {
    int idx = blockIdx.x * blockDim.x + threadIdx.x;
    if (idx >= 128*384) return;
    int d = idx / 384, c = idx % 384;
    int grp = c >> 7, cc = c & 127, e = cc & 63, im = cc >> 6;
    const float* Wr = (grp == 0) ? Wqr : (grp == 1) ? Wkr : Wvr;
    const float* Wi = (grp == 0) ? Wqi : (grp == 1) ? Wki : Wvi;
    int dr = d & 63;
    float v;
    if (im == 0) v = (d < 64) ? Wr[e*64 + dr] : -Wi[e*64 + dr];
    else         v = (d < 64) ? Wi[e*64 + dr] :  Wr[e*64 + dr];
    g_Wc[idx] = v;
}

__global__ void reset_kernel() { g_active = 0; }

// ---------------- prep: rope, gates, alpha/beta/ptr recurrences ----------------
__global__ __launch_bounds__(128) void prep_kernel(const float* __restrict__ zr,
                                                   const float* __restrict__ zi,
                                                   const float* __restrict__ ctrl,
                                                   const float* __restrict__ ptr0) {
    const int b = blockIdx.x;
    const int d = threadIdx.x;            // 0..127
    const int dd = (d < 64) ? d : d - 64;
    const double freq = pow(10000.0, -((double)(2 * (dd & 31))) / 64.0);

    __shared__ float sPtrA[16], sPtrB[16];
    if (d < 16) sPtrA[d] = ptr0[b*16 + d];
    __syncthreads();

    float beta = 0.f, alpha = 1.f;
    for (int t = 0; t < TT; ++t) {
        const int bt = b*TT + t;
        float c0 = ctrl[bt*3 + 0], c1 = ctrl[bt*3 + 1], c2 = ctrl[bt*3 + 2];
        float g0 = 1.f/(1.f + expf(-c0));
        float g1 = 1.f/(1.f + expf(-c1));
        float g2 = 1.f/(1.f + expf(-c2));
        float tot = g0 + g1 + g2 + 1e-6f;
        float push = g0/tot, pop = g1/tot, stay = g2/tot;

        float ang = (float)((double)t * freq);
        float cs = cosf(ang), sn = sinf(ang);
        float vzr = zr[bt*64 + dd], vzi = zi[bt*64 + dd];
        float val = (d < 64) ? (vzr*cs - vzi*sn) : (vzr*sn + vzi*cs);

        beta  = (1.f - push)*beta + push*val;
        alpha = alpha * (1.f - push);
        g_beta[(size_t)bt*128 + d] = beta;
        if (d == 0) g_alpha[bt] = alpha;

        float* cur = (t & 1) ? sPtrB : sPtrA;
        float* nxt = (t & 1) ? sPtrA : sPtrB;
        if (d < 16) {
            int s = d;
            float np = push*cur[(s + 15) & 15] + pop*cur[(s + 1) & 15] + stay*cur[s];
            nxt[s] = np;
            g_ptrs[(size_t)bt*16 + s] = np;
        }
        __syncthreads();
    }
}

// ---------------- SGEMM: C[M x 384] = A[M x 128] @ g_Wc[128 x 384] --------------
__device__ __forceinline__ void gemm_body(const float* __restrict__ A, float* __restrict__ C) {
    __shared__ float As[8][128];
    __shared__ float Bs[8][128];
    const int tid  = threadIdx.x;
    const size_t row0 = (size_t)blockIdx.y * 128;
    const int col0 = blockIdx.x * 128;

    const int a_row = tid >> 1;
    const int a_col = (tid & 1) * 4;
    const int b_row = tid >> 5;
    const int b_col = (tid & 31) * 4;
    const int ty = tid >> 4, tx = tid & 15;

    float acc[8][8];
    #pragma unroll
    for (int i = 0; i < 8; ++i)
        #pragma unroll
        for (int j = 0; j < 8; ++j) acc[i][j] = 0.f;

    float4 pa = *(const float4*)(A + (row0 + a_row)*128 + a_col);
    float4 pb = *(const float4*)(g_Wc + (size_t)b_row*384 + col0 + b_col);

    for (int kt = 0; kt < 16; ++kt) {
        As[a_col + 0][a_row] = pa.x;
        As[a_col + 1][a_row] = pa.y;
        As[a_col + 2][a_row] = pa.z;
        As[a_col + 3][a_row] = pa.w;
        *(float4*)&Bs[b_row][b_col] = pb;
        __syncthreads();
        if (kt < 15) {
            pa = *(const float4*)(A + (row0 + a_row)*128 + (kt + 1)*8 + a_col);
            pb = *(const float4*)(g_Wc + (size_t)((kt + 1)*8 + b_row)*384 + col0 + b_col);
        }
        #pragma unroll
        for (int kk = 0; kk < 8; ++kk) {
            float4 a0 = *(float4*)&As[kk][ty*8];
            float4 a1 = *(float4*)&As[kk][ty*8 + 4];
            float4 b0 = *(float4*)&Bs[kk][tx*8];
            float4 b1 = *(float4*)&Bs[kk][tx*8 + 4];
            float ar[8] = {a0.x, a0.y, a0.z, a0.w, a1.x, a1.y, a1.z, a1.w};
            float br[8] = {b0.x, b0.y, b0.z, b0.w, b1.x, b1.y, b1.z, b1.w};
            #pragma unroll
            for (int i = 0; i < 8; ++i)
                #pragma unroll
                for (int j = 0; j < 8; ++j) acc[i][j] += ar[i]*br[j];
        }
        __syncthreads();
    }
    #pragma unroll
    for (int i = 0; i < 8; ++i) {
        size_t r = row0 + ty*8 + i;
        #pragma unroll
        for (int j = 0; j < 8; j += 4) {
            *(float4*)(C + r*384 + col0 + tx*8 + j) =
                make_float4(acc[i][j], acc[i][j+1], acc[i][j+2], acc[i][j+3]);
        }
    }
}

__global__ __launch_bounds__(256, 2) void gemm_beta_kernel() { gemm_body(g_beta, g_qkvb); }
__global__ __launch_bounds__(256, 2) void gemm_mem0_kernel(const float* __restrict__ mem0) {
    gemm_body(mem0, g_qkv0);
}

// ---------------- per-batch scan --------------------------------------------
#define ST 388  // padded slot stride for sM0

__global__ __launch_bounds__(256) void scan_kernel(const float* __restrict__ mem0,
                                                   float* __restrict__ out) {
    const int b = blockIdx.x;
    const int tid = threadIdx.x;

    __shared__ float sM0[16*ST];     // per-slot: q0f(128)|k0f(128)|v0f(128), padded
    __shared__ float sG0[256];
    __shared__ float sQKVB[384];
    __shared__ float sU[16], sW[16];
    __shared__ float sE, sAlphaS;
    __shared__ float sPAT[16*17];
    __shared__ float sC[16];
    __shared__ float sPtr[16];

    const float* base0 = g_qkv0 + (size_t)b*16*384;
    for (int i = tid; i < 16*384; i += 256)
        sM0[(i/384)*ST + (i % 384)] = base0[i];
    __syncthreads();

    // G0[s][j] = qf0[s] . kf0[j]  (thread tid == s*16+j, read back by the same thread)
    {
        int s = tid >> 4, j = tid & 15;
        const float* q = &sM0[s*ST];
        const float* k = &sM0[j*ST + 128];
        float acc = 0.f;
        #pragma unroll 8
        for (int d = 0; d < 128; ++d) acc += q[d]*k[d];
        sG0[tid] = acc;
    }

    const int wgroup = tid >> 3;  // dot id 0..31
    const int l8 = tid & 7;

    for (int t = 0; t < TT; ++t) {
        const size_t bt = (size_t)b*TT + t;
        const float* bb = g_qkvb + bt*384;
        for (int i = tid; i < 384; i += 256) sQKVB[i] = bb[i];
        if (tid < 16) sPtr[tid] = g_ptrs[bt*16 + tid];
        if (tid == 0) sAlphaS = g_alpha[bt];
        __syncthreads();

        // u[s] = qf0[s].kbeta ; w[j] = qbeta.kf0[j]
        {
            float acc = 0.f;
            if (wgroup < 16) {
                const float* q = &sM0[wgroup*ST];
                #pragma unroll
                for (int i2 = 0; i2 < 16; ++i2) { int d = l8 + 8*i2; acc += q[d]*sQKVB[128 + d]; }
            } else {
                const float* k = &sM0[(wgroup - 16)*ST + 128];
                #pragma unroll
                for (int i2 = 0; i2 < 16; ++i2) { int d = l8 + 8*i2; acc += k[d]*sQKVB[d]; }
            }
            acc += __shfl_xor_sync(0xffffffffu, acc, 4, 8);
            acc += __shfl_xor_sync(0xffffffffu, acc, 2, 8);
            acc += __shfl_xor_sync(0xffffffffu, acc, 1, 8);
            if (l8 == 0) {
                if (wgroup < 16) sU[wgroup] = acc;
                else             sW[wgroup - 16] = acc;
            }
            if (tid < 32) {  // e = qbeta . kbeta (warp 0)
                float pe = 0.f;
                #pragma unroll
                for (int i2 = 0; i2 < 4; ++i2) { int d = tid + 32*i2; pe += sQKVB[d]*sQKVB[128 + d]; }
                pe += __shfl_xor_sync(0xffffffffu, pe, 16);
                pe += __shfl_xor_sync(0xffffffffu, pe, 8);
                pe += __shfl_xor_sync(0xffffffffu, pe, 4);
                pe += __shfl_xor_sync(0xffffffffu, pe, 2);
                pe += __shfl_xor_sync(0xffffffffu, pe, 1);
                if (tid == 0) sE = pe;
            }
        }
        __syncthreads();

        // logits + softmax (thread (s,j)); then p*attn into transposed smem
        {
            const float alpha = sAlphaS;
            const float a2 = alpha*alpha;
            int s = tid >> 4, j = tid & 15;
            float L = 0.125f * (a2*sG0[tid] + alpha*(sU[s] + sW[j]) + sE);
            float m = L;
            m = fmaxf(m, __shfl_xor_sync(0xffffffffu, m, 8, 16));
            m = fmaxf(m, __shfl_xor_sync(0xffffffffu, m, 4, 16));
            m = fmaxf(m, __shfl_xor_sync(0xffffffffu, m, 2, 16));
            m = fmaxf(m, __shfl_xor_sync(0xffffffffu, m, 1, 16));
            float ex = expf(L - m);
            float sum = ex;
            sum += __shfl_xor_sync(0xffffffffu, sum, 8, 16);
            sum += __shfl_xor_sync(0xffffffffu, sum, 4, 16);
            sum += __shfl_xor_sync(0xffffffffu, sum, 2, 16);
            sum += __shfl_xor_sync(0xffffffffu, sum, 1, 16);
            float attn = ex / sum;
            sPAT[j*17 + s] = sPtr[s] * attn;
        }
        __syncthreads();

        if (tid < 16) {  // c[j] = sum_s ptr[s]*attn[s][j]
            float c = 0.f;
            #pragma unroll
            for (int s2 = 0; s2 < 16; ++s2) c += sPAT[tid*17 + s2];
            sC[tid] = c;
        }
        __syncthreads();

        if (tid < 128) {  // read[d] = alpha * sum_j c[j]*v0f[j][d] + (sum_j c[j]) * vbeta[d]
            const float alpha = sAlphaS;
            float r = 0.f, csum = 0.f;
            #pragma unroll
            for (int j = 0; j < 16; ++j) {
                float cj = sC[j];
                csum += cj;
                r += cj * sM0[j*ST + 256 + tid];
            }
            out[((size_t)t*BATCH + b)*128 + tid] = alpha*r + csum*sQKVB[256 + tid];
        }
        __syncthreads();
    }

    // epilogue: mem_f = alpha_T*mem0 + beta_T ; ptr_f ; active count
    const float alphaT = g_alpha[(size_t)b*TT + (TT - 1)];
    const float* betaT = g_beta + ((size_t)b*TT + (TT - 1))*128;
    if (tid < 128) sQKVB[tid] = betaT[tid];
    __syncthreads();

    float* out_mem = out + (size_t)TT*BATCH*128;
    const float* m0 = mem0 + (size_t)b*2048;
    for (int i = tid; i < 2048; i += 256)
        out_mem[(size_t)b*2048 + i] = alphaT*m0[i] + sQKVB[i & 127];

    float* out_ptr = out + (size_t)TT*BATCH*128 + (size_t)BATCH*2048;
    if (tid < 16) {
        float pv = g_ptrs[((size_t)b*TT + (TT - 1))*16 + tid];
        out_ptr[(size_t)b*16 + tid] = pv;
        int cnt = (pv > 0.1f) ? 1 : 0;
        cnt += __shfl_xor_sync(0x0000ffffu, cnt, 8, 16);
        cnt += __shfl_xor_sync(0x0000ffffu, cnt, 4, 16);
        cnt += __shfl_xor_sync(0x0000ffffu, cnt, 2, 16);
        cnt += __shfl_xor_sync(0x0000ffffu, cnt, 1, 16);
        if (tid == 0) atomicAdd(&g_active, cnt);
    }
}

__global__ void finalize_kernel(float* __restrict__ out) {
    out[(size_t)TT*BATCH*128 + (size_t)BATCH*2048 + (size_t)BATCH*16] =
        (float)g_active / (float)BATCH;
}

// ---------------- launcher ----------------------------------------------------
extern "C" void kernel_launch(void* const* d_in, const int* in_sizes, int n_in,
                              void* d_out, int out_size) {
    const float* zr   = (const float*)d_in[0];
    const float* zi   = (const float*)d_in[1];
    const float* ctrl = (const float*)d_in[2];
    const float* mem0 = (const float*)d_in[3];
    const float* ptr0 = (const float*)d_in[4];
    const float* Wqr  = (const float*)d_in[5];
    const float* Wqi  = (const float*)d_in[6];
    const float* Wkr  = (const float*)d_in[7];
    const float* Wki  = (const float*)d_in[8];
    const float* Wvr  = (const float*)d_in[9];
    const float* Wvi  = (const float*)d_in[10];
    float* out = (float*)d_out;

    build_wc_kernel<<<192, 256>>>(Wqr, Wqi, Wkr, Wki, Wvr, Wvi);
    reset_kernel<<<1, 1>>>();
    prep_kernel<<<BATCH, 128>>>(zr, zi, ctrl, ptr0);
    gemm_beta_kernel<<<dim3(3, NROWS_B/128), 256>>>();
    gemm_mem0_kernel<<<dim3(3, NROWS_0/128), 256>>>(mem0);
    scan_kernel<<<BATCH, 256>>>(mem0, out);
    finalize_kernel<<<1, 1>>>(out);
}

// round 3
// speedup vs baseline: 1.2239x; 1.2239x over previous
#include <cuda_runtime.h>
#include <cuda_bf16.h>
#include <math.h>
#include <stdint.h>

#define BATCH 16384
#define TT 32
#define SS 16
#define NROWS_B (BATCH*TT)   // 524288
#define NROWS_0 (BATCH*SS)   // 262144

// ---------------- scratch (device globals; no allocations allowed) -------------
__device__ float g_beta[(size_t)NROWS_B*128];   // beta_{b,t} (128) fp32
__device__ float g_qkvb[(size_t)NROWS_B*384];   // clin(beta): q|k|v
__device__ float g_qkv0[(size_t)NROWS_0*384];   // clin(mem0)
__device__ float g_alpha[NROWS_B];
__device__ float g_ptrs[(size_t)NROWS_B*16];
__device__ unsigned short g_Wt_hi[384*128];     // W^T split hi (bf16 bits): row n, col d
__device__ unsigned short g_Wt_lo[384*128];
__device__ int   g_active;

// ---------------- build combined transposed/split weight -----------------------
__global__ void build_wt_kernel(const float* __restrict__ Wqr, const float* __restrict__ Wqi,
                                const float* __restrict__ Wkr, const float* __restrict__ Wki,
                                const float* __restrict__ Wvr, const float* __restrict__ Wvi) {
    int idx = blockIdx.x * blockDim.x + threadIdx.x;
    if (idx >= 384*128) return;
    int n = idx / 128, d = idx % 128;          // n = output col, d = input dim
    int grp = n >> 7, cc = n & 127, e = cc & 63, im = cc >> 6;
    const float* Wr = (grp == 0) ? Wqr : (grp == 1) ? Wkr : Wvr;
    const float* Wi = (grp == 0) ? Wqi : (grp == 1) ? Wki : Wvi;
    int dr = d & 63;
    float v;
    if (im == 0) v = (d < 64) ? Wr[e*64 + dr] : -Wi[e*64 + dr];
    else         v = (d < 64) ? Wi[e*64 + dr] :  Wr[e*64 + dr];
    __nv_bfloat16 h = __float2bfloat16(v);
    float lo = v - __bfloat162float(h);
    __nv_bfloat16 l = __float2bfloat16(lo);
    g_Wt_hi[idx] = __bfloat16_as_ushort(h);
    g_Wt_lo[idx] = __bfloat16_as_ushort(l);
}

__global__ void reset_kernel() { g_active = 0; }

// ---------------- prep: rope, gates, alpha/beta/ptr recurrences ----------------
__global__ __launch_bounds__(128) void prep_kernel(const float* __restrict__ zr,
                                                   const float* __restrict__ zi,
                                                   const float* __restrict__ ctrl,
                                                   const float* __restrict__ ptr0) {
    const int b = blockIdx.x;
    const int d = threadIdx.x;            // 0..127
    const int dd = (d < 64) ? d : d - 64;
    const double freq = pow(10000.0, -((double)(2 * (dd & 31))) / 64.0);

    __shared__ float sPtrA[16], sPtrB[16];
    if (d < 16) sPtrA[d] = ptr0[b*16 + d];
    __syncthreads();

    float beta = 0.f, alpha = 1.f;
    for (int t = 0; t < TT; ++t) {
        const int bt = b*TT + t;
        float c0 = ctrl[bt*3 + 0], c1 = ctrl[bt*3 + 1], c2 = ctrl[bt*3 + 2];
        float g0 = 1.f/(1.f + expf(-c0));
        float g1 = 1.f/(1.f + expf(-c1));
        float g2 = 1.f/(1.f + expf(-c2));
        float tot = g0 + g1 + g2 + 1e-6f;
        float push = g0/tot, pop = g1/tot, stay = g2/tot;

        float ang = (float)((double)t * freq);
        float cs = cosf(ang), sn = sinf(ang);
        float vzr = zr[bt*64 + dd], vzi = zi[bt*64 + dd];
        float val = (d < 64) ? (vzr*cs - vzi*sn) : (vzr*sn + vzi*cs);

        beta  = (1.f - push)*beta + push*val;
        alpha = alpha * (1.f - push);
        g_beta[(size_t)bt*128 + d] = beta;
        if (d == 0) g_alpha[bt] = alpha;

        float* cur = (t & 1) ? sPtrB : sPtrA;
        float* nxt = (t & 1) ? sPtrA : sPtrB;
        if (d < 16) {
            int s = d;
            float np = push*cur[(s + 15) & 15] + pop*cur[(s + 1) & 15] + stay*cur[s];
            nxt[s] = np;
            g_ptrs[(size_t)bt*16 + s] = np;
        }
        __syncthreads();
    }
}

// ---------------- HMMA split-bf16 GEMM: C[M x 384] = A[M x 128] @ W -------------
// block: 128 rows, loops over 3 col-blocks of 128; 256 threads (8 warps).
// warp tile 32(M) x 64(N) via m16n8k16: 2 m-tiles x 8 n-tiles.
#define ASTRIDE 136            // halves per row (pad 8 -> conflict-free frag loads)
#define SM_AHI 0
#define SM_ALO (128*ASTRIDE*2)
#define SM_BHI (2*128*ASTRIDE*2)
#define SM_BLO (3*128*ASTRIDE*2)
#define SM_TOTAL (4*128*ASTRIDE*2)   // 139264 bytes

__device__ __forceinline__ void mma16816(float* d, const uint32_t* a, const uint32_t* b) {
    asm volatile(
        "mma.sync.aligned.m16n8k16.row.col.f32.bf16.bf16.f32 "
        "{%0,%1,%2,%3},{%4,%5,%6,%7},{%8,%9},{%0,%1,%2,%3};"
        : "+f"(d[0]), "+f"(d[1]), "+f"(d[2]), "+f"(d[3])
        : "r"(a[0]), "r"(a[1]), "r"(a[2]), "r"(a[3]), "r"(b[0]), "r"(b[1]));
}

__device__ __forceinline__ void hmma_body(const float* __restrict__ A, float* __restrict__ C) {
    extern __shared__ char smem[];
    unsigned short* sAhi = (unsigned short*)(smem + SM_AHI);
    unsigned short* sAlo = (unsigned short*)(smem + SM_ALO);
    unsigned short* sBhi = (unsigned short*)(smem + SM_BHI);
    unsigned short* sBlo = (unsigned short*)(smem + SM_BLO);

    const int tid = threadIdx.x;
    const int wid = tid >> 5;
    const int lane = tid & 31;
    const int gid = lane >> 2;       // 0..7
    const int tig = lane & 3;        // 0..3
    const int wr = wid & 3;          // warp row group (4 x 32 rows)
    const int wc = wid >> 2;         // warp col group (2 x 64 cols)
    const size_t row0 = (size_t)blockIdx.x * 128;

    // ---- stage A tile [128 x 128] fp32 -> split bf16 hi/lo ----
    {
        const float* Ab = A + row0*128;
        #pragma unroll
        for (int it = 0; it < 16; ++it) {
            int i = tid + it*256;                    // 0..4095
            int r = i >> 5, k = (i & 31) * 4;
            float4 v = *(const float4*)(Ab + (size_t)r*128 + k);
            __nv_bfloat16 h0 = __float2bfloat16(v.x);
            __nv_bfloat16 h1 = __float2bfloat16(v.y);
            __nv_bfloat16 h2 = __float2bfloat16(v.z);
            __nv_bfloat16 h3 = __float2bfloat16(v.w);
            __nv_bfloat16 l0 = __float2bfloat16(v.x - __bfloat162float(h0));
            __nv_bfloat16 l1 = __float2bfloat16(v.y - __bfloat162float(h1));
            __nv_bfloat16 l2 = __float2bfloat16(v.z - __bfloat162float(h2));
            __nv_bfloat16 l3 = __float2bfloat16(v.w - __bfloat162float(h3));
            uint64_t hv = (uint64_t)__bfloat16_as_ushort(h0)
                        | ((uint64_t)__bfloat16_as_ushort(h1) << 16)
                        | ((uint64_t)__bfloat16_as_ushort(h2) << 32)
                        | ((uint64_t)__bfloat16_as_ushort(h3) << 48);
            uint64_t lv = (uint64_t)__bfloat16_as_ushort(l0)
                        | ((uint64_t)__bfloat16_as_ushort(l1) << 16)
                        | ((uint64_t)__bfloat16_as_ushort(l2) << 32)
                        | ((uint64_t)__bfloat16_as_ushort(l3) << 48);
            *(uint64_t*)&sAhi[r*ASTRIDE + k] = hv;
            *(uint64_t*)&sAlo[r*ASTRIDE + k] = lv;
        }
    }

    for (int cb = 0; cb < 3; ++cb) {
        const int col0 = cb * 128;
        __syncthreads();   // A staged (cb=0) / previous col-block mma done (cb>0)

        // ---- stage B tile: rows col0..col0+127 of W^T, bf16 hi/lo ----
        #pragma unroll
        for (int it = 0; it < 8; ++it) {
            int i = tid + it*256;                    // 0..2047
            int r = i >> 4, k = (i & 15) * 8;
            size_t gidx = (size_t)(col0 + r)*128 + k;
            *(uint4*)&sBhi[r*ASTRIDE + k] = *(const uint4*)(g_Wt_hi + gidx);
            *(uint4*)&sBlo[r*ASTRIDE + k] = *(const uint4*)(g_Wt_lo + gidx);
        }
        __syncthreads();

        float acc[2][8][4];
        #pragma unroll
        for (int m = 0; m < 2; ++m)
            #pragma unroll
            for (int j = 0; j < 8; ++j)
                #pragma unroll
                for (int q = 0; q < 4; ++q) acc[m][j][q] = 0.f;

        #pragma unroll
        for (int kk = 0; kk < 8; ++kk) {
            const int k0 = kk*16 + 2*tig;
            uint32_t ah[2][4], al[2][4];
            #pragma unroll
            for (int m = 0; m < 2; ++m) {
                int r = wr*32 + m*16 + gid;
                ah[m][0] = *(const uint32_t*)&sAhi[r*ASTRIDE + k0];
                ah[m][1] = *(const uint32_t*)&sAhi[(r+8)*ASTRIDE + k0];
                ah[m][2] = *(const uint32_t*)&sAhi[r*ASTRIDE + k0 + 8];
                ah[m][3] = *(const uint32_t*)&sAhi[(r+8)*ASTRIDE + k0 + 8];
                al[m][0] = *(const uint32_t*)&sAlo[r*ASTRIDE + k0];
                al[m][1] = *(const uint32_t*)&sAlo[(r+8)*ASTRIDE + k0];
                al[m][2] = *(const uint32_t*)&sAlo[r*ASTRIDE + k0 + 8];
                al[m][3] = *(const uint32_t*)&sAlo[(r+8)*ASTRIDE + k0 + 8];
            }
            #pragma unroll
            for (int j = 0; j < 8; ++j) {
                int n = wc*64 + j*8 + gid;
                uint32_t bh[2], bl[2];
                bh[0] = *(const uint32_t*)&sBhi[n*ASTRIDE + k0];
                bh[1] = *(const uint32_t*)&sBhi[n*ASTRIDE + k0 + 8];
                bl[0] = *(const uint32_t*)&sBlo[n*ASTRIDE + k0];
                bl[1] = *(const uint32_t*)&sBlo[n*ASTRIDE + k0 + 8];
                mma16816(acc[0][j], ah[0], bh);
                mma16816(acc[1][j], ah[1], bh);
                mma16816(acc[0][j], ah[0], bl);
                mma16816(acc[1][j], ah[1], bl);
                mma16816(acc[0][j], al[0], bh);
                mma16816(acc[1][j], al[1], bh);
            }
        }

        // ---- epilogue: direct gmem stores (cols contiguous pairs) ----
        #pragma unroll
        for (int m = 0; m < 2; ++m) {
            size_t r = row0 + wr*32 + m*16 + gid;
            #pragma unroll
            for (int j = 0; j < 8; ++j) {
                int c = col0 + wc*64 + j*8 + 2*tig;
                *(float2*)(C + r*384 + c)       = make_float2(acc[m][j][0], acc[m][j][1]);
                *(float2*)(C + (r+8)*384 + c)   = make_float2(acc[m][j][2], acc[m][j][3]);
            }
        }
    }
}

__global__ __launch_bounds__(256, 1) void gemm_beta_kernel() { hmma_body(g_beta, g_qkvb); }
__global__ __launch_bounds__(256, 1) void gemm_mem0_kernel(const float* __restrict__ mem0) {
    hmma_body(mem0, g_qkv0);
}

// ---------------- per-batch scan --------------------------------------------
#define ST 388  // padded slot stride for sM0

__global__ __launch_bounds__(256) void scan_kernel(const float* __restrict__ mem0,
                                                   float* __restrict__ out) {
    const int b = blockIdx.x;
    const int tid = threadIdx.x;

    __shared__ float sM0[16*ST];     // per-slot: q0f(128)|k0f(128)|v0f(128), padded
    __shared__ float sG0[256];
    __shared__ float sQKVB[384];
    __shared__ float sU[16], sW[16];
    __shared__ float sE, sAlphaS;
    __shared__ float sPAT[16*17];
    __shared__ float sC[16];
    __shared__ float sPtr[16];

    const float* base0 = g_qkv0 + (size_t)b*16*384;
    for (int i = tid; i < 16*384; i += 256)
        sM0[(i/384)*ST + (i % 384)] = base0[i];
    __syncthreads();

    // G0[s][j] = qf0[s] . kf0[j]
    {
        int s = tid >> 4, j = tid & 15;
        const float* q = &sM0[s*ST];
        const float* k = &sM0[j*ST + 128];
        float acc = 0.f;
        #pragma unroll 8
        for (int d = 0; d < 128; ++d) acc += q[d]*k[d];
        sG0[tid] = acc;
    }

    const int wgroup = tid >> 3;  // dot id 0..31
    const int l8 = tid & 7;

    for (int t = 0; t < TT; ++t) {
        const size_t bt = (size_t)b*TT + t;
        const float* bb = g_qkvb + bt*384;
        for (int i = tid; i < 384; i += 256) sQKVB[i] = bb[i];
        if (tid < 16) sPtr[tid] = g_ptrs[bt*16 + tid];
        if (tid == 0) sAlphaS = g_alpha[bt];
        __syncthreads();

        // u[s] = qf0[s].kbeta ; w[j] = qbeta.kf0[j]
        {
            float acc = 0.f;
            if (wgroup < 16) {
                const float* q = &sM0[wgroup*ST];
                #pragma unroll
                for (int i2 = 0; i2 < 16; ++i2) { int d = l8 + 8*i2; acc += q[d]*sQKVB[128 + d]; }
            } else {
                const float* k = &sM0[(wgroup - 16)*ST + 128];
                #pragma unroll
                for (int i2 = 0; i2 < 16; ++i2) { int d = l8 + 8*i2; acc += k[d]*sQKVB[d]; }
            }
            acc += __shfl_xor_sync(0xffffffffu, acc, 4, 8);
            acc += __shfl_xor_sync(0xffffffffu, acc, 2, 8);
            acc += __shfl_xor_sync(0xffffffffu, acc, 1, 8);
            if (l8 == 0) {
                if (wgroup < 16) sU[wgroup] = acc;
                else             sW[wgroup - 16] = acc;
            }
            if (tid < 32) {  // e = qbeta . kbeta
                float pe = 0.f;
                #pragma unroll
                for (int i2 = 0; i2 < 4; ++i2) { int d = tid + 32*i2; pe += sQKVB[d]*sQKVB[128 + d]; }
                pe += __shfl_xor_sync(0xffffffffu, pe, 16);
                pe += __shfl_xor_sync(0xffffffffu, pe, 8);
                pe += __shfl_xor_sync(0xffffffffu, pe, 4);
                pe += __shfl_xor_sync(0xffffffffu, pe, 2);
                pe += __shfl_xor_sync(0xffffffffu, pe, 1);
                if (tid == 0) sE = pe;
            }
        }
        __syncthreads();

        // logits + softmax (thread (s,j)); p*attn into transposed smem
        {
            const float alpha = sAlphaS;
            const float a2 = alpha*alpha;
            int s = tid >> 4, j = tid & 15;
            float L = 0.125f * (a2*sG0[tid] + alpha*(sU[s] + sW[j]) + sE);
            float m = L;
            m = fmaxf(m, __shfl_xor_sync(0xffffffffu, m, 8, 16));
            m = fmaxf(m, __shfl_xor_sync(0xffffffffu, m, 4, 16));
            m = fmaxf(m, __shfl_xor_sync(0xffffffffu, m, 2, 16));
            m = fmaxf(m, __shfl_xor_sync(0xffffffffu, m, 1, 16));
            float ex = expf(L - m);
            float sum = ex;
            sum += __shfl_xor_sync(0xffffffffu, sum, 8, 16);
            sum += __shfl_xor_sync(0xffffffffu, sum, 4, 16);
            sum += __shfl_xor_sync(0xffffffffu, sum, 2, 16);
            sum += __shfl_xor_sync(0xffffffffu, sum, 1, 16);
            float attn = ex / sum;
            sPAT[j*17 + s] = sPtr[s] * attn;
        }
        __syncthreads();

        if (tid < 16) {  // c[j] = sum_s ptr[s]*attn[s][j]
            float c = 0.f;
            #pragma unroll
            for (int s2 = 0; s2 < 16; ++s2) c += sPAT[tid*17 + s2];
            sC[tid] = c;
        }
        __syncthreads();

        if (tid < 128) {  // read[d] = alpha * sum_j c[j]*v0f[j][d] + csum * vbeta[d]
            const float alpha = sAlphaS;
            float r = 0.f, csum = 0.f;
            #pragma unroll
            for (int j = 0; j < 16; ++j) {
                float cj = sC[j];
                csum += cj;
                r += cj * sM0[j*ST + 256 + tid];
            }
            out[((size_t)t*BATCH + b)*128 + tid] = alpha*r + csum*sQKVB[256 + tid];
        }
        __syncthreads();
    }

    // epilogue: mem_f = alpha_T*mem0 + beta_T ; ptr_f ; active count
    const float alphaT = g_alpha[(size_t)b*TT + (TT - 1)];
    const float* betaT = g_beta + ((size_t)b*TT + (TT - 1))*128;
    if (tid < 128) sQKVB[tid] = betaT[tid];
    __syncthreads();

    float* out_mem = out + (size_t)TT*BATCH*128;
    const float* m0 = mem0 + (size_t)b*2048;
    for (int i = tid; i < 2048; i += 256)
        out_mem[(size_t)b*2048 + i] = alphaT*m0[i] + sQKVB[i & 127];

    float* out_ptr = out + (size_t)TT*BATCH*128 + (size_t)BATCH*2048;
    if (tid < 16) {
        float pv = g_ptrs[((size_t)b*TT + (TT - 1))*16 + tid];
        out_ptr[(size_t)b*16 + tid] = pv;
        int cnt = (pv > 0.1f) ? 1 : 0;
        cnt += __shfl_xor_sync(0x0000ffffu, cnt, 8, 16);
        cnt += __shfl_xor_sync(0x0000ffffu, cnt, 4, 16);
        cnt += __shfl_xor_sync(0x0000ffffu, cnt, 2, 16);
        cnt += __shfl_xor_sync(0x0000ffffu, cnt, 1, 16);
        if (tid == 0) atomicAdd(&g_active, cnt);
    }
}

__global__ void finalize_kernel(float* __restrict__ out) {
    out[(size_t)TT*BATCH*128 + (size_t)BATCH*2048 + (size_t)BATCH*16] =
        (float)g_active / (float)BATCH;
}

// ---------------- launcher ----------------------------------------------------
extern "C" void kernel_launch(void* const* d_in, const int* in_sizes, int n_in,
                              void* d_out, int out_size) {
    const float* zr   = (const float*)d_in[0];
    const float* zi   = (const float*)d_in[1];
    const float* ctrl = (const float*)d_in[2];
    const float* mem0 = (const float*)d_in[3];
    const float* ptr0 = (const float*)d_in[4];
    const float* Wqr  = (const float*)d_in[5];
    const float* Wqi  = (const float*)d_in[6];
    const float* Wkr  = (const float*)d_in[7];
    const float* Wki  = (const float*)d_in[8];
    const float* Wvr  = (const float*)d_in[9];
    const float* Wvi  = (const float*)d_in[10];
    float* out = (float*)d_out;

    static bool attr_done = false;
    if (!attr_done) {
        cudaFuncSetAttribute(gemm_beta_kernel, cudaFuncAttributeMaxDynamicSharedMemorySize, SM_TOTAL);
        cudaFuncSetAttribute(gemm_mem0_kernel, cudaFuncAttributeMaxDynamicSharedMemorySize, SM_TOTAL);
        attr_done = true;
    }

    build_wt_kernel<<<192, 256>>>(Wqr, Wqi, Wkr, Wki, Wvr, Wvi);
    reset_kernel<<<1, 1>>>();
    prep_kernel<<<BATCH, 128>>>(zr, zi, ctrl, ptr0);

    gemm_beta_kernel<<<NROWS_B/128, 256, SM_TOTAL>>>();
    gemm_mem0_kernel<<<NROWS_0/128, 256, SM_TOTAL>>>(mem0);

    scan_kernel<<<BATCH, 256>>>(mem0, out);
    finalize_kernel<<<1, 1>>>(out);
}

// round 4
// speedup vs baseline: 1.8517x; 1.5129x over previous
#include <cuda_runtime.h>
#include <cuda_bf16.h>
#include <math.h>
#include <stdint.h>

#define BATCH 16384
#define TT 32
#define SS 16
#define NROWS_B (BATCH*TT)   // 524288
#define NROWS_0 (BATCH*SS)   // 262144

// ---------------- scratch (device globals; no allocations allowed) -------------
__device__ unsigned short g_beta_hi[(size_t)NROWS_B*128];  // beta split bf16 hi
__device__ unsigned short g_beta_lo[(size_t)NROWS_B*128];  // beta split bf16 lo
__device__ float g_qkvb[(size_t)NROWS_B*384];   // clin(beta): q|k|v
__device__ float g_qkv0[(size_t)NROWS_0*384];   // clin(mem0)
__device__ float g_alpha[NROWS_B];
__device__ float g_ptrs[(size_t)NROWS_B*16];
__device__ unsigned short g_Wt_hi[384*128];     // W^T split hi (bf16 bits): row n, col d
__device__ unsigned short g_Wt_lo[384*128];
__device__ int   g_active;

// ---------------- build combined transposed/split weight -----------------------
__global__ void build_wt_kernel(const float* __restrict__ Wqr, const float* __restrict__ Wqi,
                                const float* __restrict__ Wkr, const float* __restrict__ Wki,
                                const float* __restrict__ Wvr, const float* __restrict__ Wvi) {
    int idx = blockIdx.x * blockDim.x + threadIdx.x;
    if (idx >= 384*128) return;
    int n = idx / 128, d = idx % 128;          // n = output col, d = input dim
    int grp = n >> 7, cc = n & 127, e = cc & 63, im = cc >> 6;
    const float* Wr = (grp == 0) ? Wqr : (grp == 1) ? Wkr : Wvr;
    const float* Wi = (grp == 0) ? Wqi : (grp == 1) ? Wki : Wvi;
    int dr = d & 63;
    float v;
    if (im == 0) v = (d < 64) ? Wr[e*64 + dr] : -Wi[e*64 + dr];
    else         v = (d < 64) ? Wi[e*64 + dr] :  Wr[e*64 + dr];
    __nv_bfloat16 h = __float2bfloat16(v);
    float lo = v - __bfloat162float(h);
    __nv_bfloat16 l = __float2bfloat16(lo);
    g_Wt_hi[idx] = __bfloat16_as_ushort(h);
    g_Wt_lo[idx] = __bfloat16_as_ushort(l);
}

__global__ void reset_kernel() { g_active = 0; }

// ---------------- prep: rope, gates, alpha/beta/ptr recurrences ----------------
__global__ __launch_bounds__(128) void prep_kernel(const float* __restrict__ zr,
                                                   const float* __restrict__ zi,
                                                   const float* __restrict__ ctrl,
                                                   const float* __restrict__ ptr0) {
    const int b = blockIdx.x;
    const int d = threadIdx.x;            // 0..127
    const int dd = (d < 64) ? d : d - 64;
    const double freq = pow(10000.0, -((double)(2 * (dd & 31))) / 64.0);

    __shared__ float sPtrA[16], sPtrB[16];
    if (d < 16) sPtrA[d] = ptr0[b*16 + d];
    __syncthreads();

    float beta = 0.f, alpha = 1.f;
    for (int t = 0; t < TT; ++t) {
        const int bt = b*TT + t;
        float c0 = ctrl[bt*3 + 0], c1 = ctrl[bt*3 + 1], c2 = ctrl[bt*3 + 2];
        float g0 = 1.f/(1.f + expf(-c0));
        float g1 = 1.f/(1.f + expf(-c1));
        float g2 = 1.f/(1.f + expf(-c2));
        float tot = g0 + g1 + g2 + 1e-6f;
        float push = g0/tot, pop = g1/tot, stay = g2/tot;

        float ang = (float)((double)t * freq);
        float cs = cosf(ang), sn = sinf(ang);
        float vzr = zr[bt*64 + dd], vzi = zi[bt*64 + dd];
        float val = (d < 64) ? (vzr*cs - vzi*sn) : (vzr*sn + vzi*cs);

        beta  = (1.f - push)*beta + push*val;
        alpha = alpha * (1.f - push);

        __nv_bfloat16 h = __float2bfloat16(beta);
        __nv_bfloat16 l = __float2bfloat16(beta - __bfloat162float(h));
        g_beta_hi[(size_t)bt*128 + d] = __bfloat16_as_ushort(h);
        g_beta_lo[(size_t)bt*128 + d] = __bfloat16_as_ushort(l);
        if (d == 0) g_alpha[bt] = alpha;

        float* cur = (t & 1) ? sPtrB : sPtrA;
        float* nxt = (t & 1) ? sPtrA : sPtrB;
        if (d < 16) {
            int s = d;
            float np = push*cur[(s + 15) & 15] + pop*cur[(s + 1) & 15] + stay*cur[s];
            nxt[s] = np;
            g_ptrs[(size_t)bt*16 + s] = np;
        }
        __syncthreads();
    }
}

// ---------------- HMMA split-bf16 GEMM: C[M x 384] = A[M x 128] @ W -------------
// block: 128 rows x (3 col-blocks of 128); 256 threads (8 warps), warp tile 32x64.
// B hi/lo staged SEQUENTIALLY to halve smem -> 2 CTAs/SM.
#define ASTRIDE 136            // halves per row (pad 8 -> conflict-free frag loads)
#define SM_AHI 0
#define SM_ALO (128*ASTRIDE*2)       // 34816
#define SM_B   (2*128*ASTRIDE*2)     // 69632
#define SM_TOTAL (3*128*ASTRIDE*2)   // 104448 bytes

__device__ __forceinline__ void mma16816(float* d, const uint32_t* a, const uint32_t* b) {
    asm volatile(
        "mma.sync.aligned.m16n8k16.row.col.f32.bf16.bf16.f32 "
        "{%0,%1,%2,%3},{%4,%5,%6,%7},{%8,%9},{%0,%1,%2,%3};"
        : "+f"(d[0]), "+f"(d[1]), "+f"(d[2]), "+f"(d[3])
        : "r"(a[0]), "r"(a[1]), "r"(a[2]), "r"(a[3]), "r"(b[0]), "r"(b[1]));
}

__global__ __launch_bounds__(256, 2) void gemm_kernel(const float* __restrict__ mem0) {
    extern __shared__ char smem[];
    unsigned short* sAhi = (unsigned short*)(smem + SM_AHI);
    unsigned short* sAlo = (unsigned short*)(smem + SM_ALO);
    unsigned short* sB   = (unsigned short*)(smem + SM_B);

    const int tid = threadIdx.x;
    const int lane = tid & 31;
    const int wid = tid >> 5;
    const int gid = lane >> 2;       // 0..7
    const int tig = lane & 3;        // 0..3
    const int wr = wid & 3;          // warp row group (4 x 32 rows)
    const int wc = wid >> 2;         // warp col group (2 x 64 cols)

    const bool is_beta = (blockIdx.x < (NROWS_B/128));
    const size_t row0 = is_beta ? (size_t)blockIdx.x * 128
                                : (size_t)(blockIdx.x - NROWS_B/128) * 128;
    float* C = is_beta ? g_qkvb : g_qkv0;

    // ---- stage A tile [128 x 128] ----
    if (is_beta) {
        #pragma unroll
        for (int it = 0; it < 8; ++it) {
            int i = tid + it*256;                 // 0..2047
            int r = i >> 4, k = (i & 15) * 8;
            size_t gidx = (row0 + r)*128 + k;
            *(uint4*)&sAhi[r*ASTRIDE + k] = *(const uint4*)(g_beta_hi + gidx);
            *(uint4*)&sAlo[r*ASTRIDE + k] = *(const uint4*)(g_beta_lo + gidx);
        }
    } else {
        const float* Ab = mem0 + row0*128;
        #pragma unroll
        for (int it = 0; it < 16; ++it) {
            int i = tid + it*256;                 // 0..4095
            int r = i >> 5, k = (i & 31) * 4;
            float4 v = *(const float4*)(Ab + (size_t)r*128 + k);
            __nv_bfloat16 h0 = __float2bfloat16(v.x);
            __nv_bfloat16 h1 = __float2bfloat16(v.y);
            __nv_bfloat16 h2 = __float2bfloat16(v.z);
            __nv_bfloat16 h3 = __float2bfloat16(v.w);
            __nv_bfloat16 l0 = __float2bfloat16(v.x - __bfloat162float(h0));
            __nv_bfloat16 l1 = __float2bfloat16(v.y - __bfloat162float(h1));
            __nv_bfloat16 l2 = __float2bfloat16(v.z - __bfloat162float(h2));
            __nv_bfloat16 l3 = __float2bfloat16(v.w - __bfloat162float(h3));
            uint64_t hv = (uint64_t)__bfloat16_as_ushort(h0)
                        | ((uint64_t)__bfloat16_as_ushort(h1) << 16)
                        | ((uint64_t)__bfloat16_as_ushort(h2) << 32)
                        | ((uint64_t)__bfloat16_as_ushort(h3) << 48);
            uint64_t lv = (uint64_t)__bfloat16_as_ushort(l0)
                        | ((uint64_t)__bfloat16_as_ushort(l1) << 16)
                        | ((uint64_t)__bfloat16_as_ushort(l2) << 32)
                        | ((uint64_t)__bfloat16_as_ushort(l3) << 48);
            *(uint64_t*)&sAhi[r*ASTRIDE + k] = hv;
            *(uint64_t*)&sAlo[r*ASTRIDE + k] = lv;
        }
    }

    for (int cb = 0; cb < 3; ++cb) {
        const int col0 = cb * 128;

        float acc[2][8][4];
        #pragma unroll
        for (int m = 0; m < 2; ++m)
            #pragma unroll
            for (int j = 0; j < 8; ++j)
                #pragma unroll
                for (int q = 0; q < 4; ++q) acc[m][j][q] = 0.f;

        // -------- phase 1: B = Whi; acc += Ahi@Bhi + Alo@Bhi --------
        __syncthreads();   // A staged / prior compute done; sB free
        #pragma unroll
        for (int it = 0; it < 8; ++it) {
            int i = tid + it*256;
            int r = i >> 4, k = (i & 15) * 8;
            *(uint4*)&sB[r*ASTRIDE + k] = *(const uint4*)(g_Wt_hi + (size_t)(col0 + r)*128 + k);
        }
        __syncthreads();

        #pragma unroll
        for (int kk = 0; kk < 8; ++kk) {
            const int k0 = kk*16 + 2*tig;
            uint32_t ah[2][4], al[2][4];
            #pragma unroll
            for (int m = 0; m < 2; ++m) {
                int r = wr*32 + m*16 + gid;
                ah[m][0] = *(const uint32_t*)&sAhi[r*ASTRIDE + k0];
                ah[m][1] = *(const uint32_t*)&sAhi[(r+8)*ASTRIDE + k0];
                ah[m][2] = *(const uint32_t*)&sAhi[r*ASTRIDE + k0 + 8];
                ah[m][3] = *(const uint32_t*)&sAhi[(r+8)*ASTRIDE + k0 + 8];
                al[m][0] = *(const uint32_t*)&sAlo[r*ASTRIDE + k0];
                al[m][1] = *(const uint32_t*)&sAlo[(r+8)*ASTRIDE + k0];
                al[m][2] = *(const uint32_t*)&sAlo[r*ASTRIDE + k0 + 8];
                al[m][3] = *(const uint32_t*)&sAlo[(r+8)*ASTRIDE + k0 + 8];
            }
            #pragma unroll
            for (int j = 0; j < 8; ++j) {
                int n = wc*64 + j*8 + gid;
                uint32_t bb[2];
                bb[0] = *(const uint32_t*)&sB[n*ASTRIDE + k0];
                bb[1] = *(const uint32_t*)&sB[n*ASTRIDE + k0 + 8];
                mma16816(acc[0][j], ah[0], bb);
                mma16816(acc[1][j], ah[1], bb);
                mma16816(acc[0][j], al[0], bb);
                mma16816(acc[1][j], al[1], bb);
            }
        }

        // -------- phase 2: B = Wlo; acc += Ahi@Blo --------
        __syncthreads();
        #pragma unroll
        for (int it = 0; it < 8; ++it) {
            int i = tid + it*256;
            int r = i >> 4, k = (i & 15) * 8;
            *(uint4*)&sB[r*ASTRIDE + k] = *(const uint4*)(g_Wt_lo + (size_t)(col0 + r)*128 + k);
        }
        __syncthreads();

        #pragma unroll
        for (int kk = 0; kk < 8; ++kk) {
            const int k0 = kk*16 + 2*tig;
            uint32_t ah[2][4];
            #pragma unroll
            for (int m = 0; m < 2; ++m) {
                int r = wr*32 + m*16 + gid;
                ah[m][0] = *(const uint32_t*)&sAhi[r*ASTRIDE + k0];
                ah[m][1] = *(const uint32_t*)&sAhi[(r+8)*ASTRIDE + k0];
                ah[m][2] = *(const uint32_t*)&sAhi[r*ASTRIDE + k0 + 8];
                ah[m][3] = *(const uint32_t*)&sAhi[(r+8)*ASTRIDE + k0 + 8];
            }
            #pragma unroll
            for (int j = 0; j < 8; ++j) {
                int n = wc*64 + j*8 + gid;
                uint32_t bb[2];
                bb[0] = *(const uint32_t*)&sB[n*ASTRIDE + k0];
                bb[1] = *(const uint32_t*)&sB[n*ASTRIDE + k0 + 8];
                mma16816(acc[0][j], ah[0], bb);
                mma16816(acc[1][j], ah[1], bb);
            }
        }

        // ---- epilogue: direct gmem stores ----
        #pragma unroll
        for (int m = 0; m < 2; ++m) {
            size_t r = row0 + wr*32 + m*16 + gid;
            #pragma unroll
            for (int j = 0; j < 8; ++j) {
                int c = col0 + wc*64 + j*8 + 2*tig;
                *(float2*)(C + r*384 + c)       = make_float2(acc[m][j][0], acc[m][j][1]);
                *(float2*)(C + (r+8)*384 + c)   = make_float2(acc[m][j][2], acc[m][j][3]);
            }
        }
    }
}

// ---------------- per-batch scan (t-parallel, 8 t per iteration) ---------------
#define ST 388   // padded slot stride (floats) for sM0
#define QST 392  // padded stride for qkvb chunk

__global__ __launch_bounds__(256) void scan_kernel(const float* __restrict__ mem0,
                                                   float* __restrict__ out) {
    const int b = blockIdx.x;
    const int tid = threadIdx.x;

    __shared__ float sM0[16*ST];       // per-slot: q0f(128)|k0f(128)|v0f(128)
    __shared__ float sG0[16*17];       // G0[s][j], stride 17 (conflict-free)
    __shared__ float sQ[8*QST];        // qkvb for 8 t
    __shared__ float sW8[8][16];
    __shared__ float sPA[8*272];       // ptr[s]*attn[s][j], [t][s*17+j]
    __shared__ float sC8[8][16];
    __shared__ float sPtr8[8][16];
    __shared__ float sAl8[8];

    const float* base0 = g_qkv0 + (size_t)b*16*384;
    for (int i = tid; i < 16*384; i += 256)
        sM0[(i/384)*ST + (i % 384)] = base0[i];
    __syncthreads();

    // G0[s][j] = qf0[s] . kf0[j]
    {
        int s = tid >> 4, j = tid & 15;
        const float* q = &sM0[s*ST];
        const float* k = &sM0[j*ST + 128];
        float acc = 0.f;
        #pragma unroll 8
        for (int d = 0; d < 128; ++d) acc += q[d]*k[d];
        sG0[s*17 + j] = acc;
    }

    for (int tc = 0; tc < 4; ++tc) {
        const int t0 = tc*8;
        const size_t bt0 = (size_t)b*TT + t0;

        // stage qkvb / ptr / alpha for 8 t
        {
            const float* bb = g_qkvb + bt0*384;
            for (int i = tid; i < 8*384; i += 256)
                sQ[(i/384)*QST + (i % 384)] = bb[i];
            if (tid < 128) {
                int t = tid >> 4, s = tid & 15;
                sPtr8[t][s] = g_ptrs[(bt0 + t)*16 + s];
            }
            if (tid < 8) sAl8[tid] = g_alpha[bt0 + tid];
        }
        __syncthreads();

        // w[t][j] = qbeta(t) . kf0[j]  (2 lanes per dot)
        {
            int t = tid >> 5, jj = tid & 31;
            int j = jj >> 1, half = jj & 1;
            const float* qb = &sQ[t*QST];
            const float* kf = &sM0[j*ST + 128];
            int d0 = half*64;
            float acc = 0.f;
            #pragma unroll 8
            for (int d = 0; d < 64; ++d) acc += qb[d0 + d]*kf[d0 + d];
            acc += __shfl_xor_sync(0xffffffffu, acc, 1);
            if (half == 0) sW8[t][j] = acc;
        }
        __syncthreads();

        // softmax per (t,s): logits = 0.125*(a^2*G0[s,j] + a*w[t][j]) (row-consts dropped)
        if (tid < 128) {
            int t = tid >> 4, s = tid & 15;
            float a = sAl8[t], a2 = a*a;
            float L[16], m = -1e30f;
            #pragma unroll
            for (int j = 0; j < 16; ++j) {
                L[j] = 0.125f*(a2*sG0[s*17 + j] + a*sW8[t][j]);
                m = fmaxf(m, L[j]);
            }
            float sum = 0.f;
            #pragma unroll
            for (int j = 0; j < 16; ++j) { L[j] = expf(L[j] - m); sum += L[j]; }
            float pscl = sPtr8[t][s] / sum;
            #pragma unroll
            for (int j = 0; j < 16; ++j) sPA[t*272 + s*17 + j] = pscl*L[j];
        }
        __syncthreads();

        // c[t][j] = sum_s ptr[s]*attn[s][j]
        if (tid < 128) {
            int t = tid >> 4, j = tid & 15;
            float c = 0.f;
            #pragma unroll
            for (int s = 0; s < 16; ++s) c += sPA[t*272 + s*17 + j];
            sC8[t][j] = c;
        }
        __syncthreads();

        // read[t][d] = a * sum_j c[j]*v0f[j][d] + csum * vbeta[d]
        {
            int t = tid >> 5, lane2 = tid & 31;
            float a = sAl8[t];
            float cj[16], csum = 0.f;
            #pragma unroll
            for (int j = 0; j < 16; ++j) { cj[j] = sC8[t][j]; csum += cj[j]; }
            float* ob = out + ((size_t)(t0 + t)*BATCH + b)*128;
            #pragma unroll
            for (int dd = 0; dd < 4; ++dd) {
                int d = lane2 + dd*32;
                float r = 0.f;
                #pragma unroll
                for (int j = 0; j < 16; ++j) r += cj[j]*sM0[j*ST + 256 + d];
                ob[d] = a*r + csum*sQ[t*QST + 256 + d];
            }
        }
        __syncthreads();
    }

    // epilogue: mem_f = alpha_T*mem0 + beta_T ; ptr_f ; active count
    const float alphaT = g_alpha[(size_t)b*TT + (TT - 1)];
    const size_t btT = ((size_t)b*TT + (TT - 1))*128;
    if (tid < 128) {
        float bh = __bfloat162float(__ushort_as_bfloat16(g_beta_hi[btT + tid]));
        float bl = __bfloat162float(__ushort_as_bfloat16(g_beta_lo[btT + tid]));
        sQ[tid] = bh + bl;
    }
    __syncthreads();

    float* out_mem = out + (size_t)TT*BATCH*128;
    const float* m0 = mem0 + (size_t)b*2048;
    for (int i = tid; i < 2048; i += 256)
        out_mem[(size_t)b*2048 + i] = alphaT*m0[i] + sQ[i & 127];

    float* out_ptr = out + (size_t)TT*BATCH*128 + (size_t)BATCH*2048;
    if (tid < 16) {
        float pv = g_ptrs[((size_t)b*TT + (TT - 1))*16 + tid];
        out_ptr[(size_t)b*16 + tid] = pv;
        int cnt = (pv > 0.1f) ? 1 : 0;
        cnt += __shfl_xor_sync(0x0000ffffu, cnt, 8, 16);
        cnt += __shfl_xor_sync(0x0000ffffu, cnt, 4, 16);
        cnt += __shfl_xor_sync(0x0000ffffu, cnt, 2, 16);
        cnt += __shfl_xor_sync(0x0000ffffu, cnt, 1, 16);
        if (tid == 0) atomicAdd(&g_active, cnt);
    }
}

__global__ void finalize_kernel(float* __restrict__ out) {
    out[(size_t)TT*BATCH*128 + (size_t)BATCH*2048 + (size_t)BATCH*16] =
        (float)g_active / (float)BATCH;
}

// ---------------- launcher ----------------------------------------------------
extern "C" void kernel_launch(void* const* d_in, const int* in_sizes, int n_in,
                              void* d_out, int out_size) {
    const float* zr   = (const float*)d_in[0];
    const float* zi   = (const float*)d_in[1];
    const float* ctrl = (const float*)d_in[2];
    const float* mem0 = (const float*)d_in[3];
    const float* ptr0 = (const float*)d_in[4];
    const float* Wqr  = (const float*)d_in[5];
    const float* Wqi  = (const float*)d_in[6];
    const float* Wkr  = (const float*)d_in[7];
    const float* Wki  = (const float*)d_in[8];
    const float* Wvr  = (const float*)d_in[9];
    const float* Wvi  = (const float*)d_in[10];
    float* out = (float*)d_out;

    cudaFuncSetAttribute(gemm_kernel, cudaFuncAttributeMaxDynamicSharedMemorySize, SM_TOTAL);

    build_wt_kernel<<<192, 256>>>(Wqr, Wqi, Wkr, Wki, Wvr, Wvi);
    reset_kernel<<<1, 1>>>();
    prep_kernel<<<BATCH, 128>>>(zr, zi, ctrl, ptr0);

    gemm_kernel<<<NROWS_B/128 + NROWS_0/128, 256, SM_TOTAL>>>(mem0);

    scan_kernel<<<BATCH, 256>>>(mem0, out);
    finalize_kernel<<<1, 1>>>(out);
}

// round 5
// speedup vs baseline: 3.0595x; 1.6523x over previous
#include <cuda_runtime.h>
#include <cuda_bf16.h>
#include <math.h>
#include <stdint.h>

#define BATCH 16384
#define TT 32
#define SS 16
#define NROWS_B (BATCH*TT)   // 524288
#define NROWS_0 (BATCH*SS)   // 262144
#define NB_BLOCKS (NROWS_B/128)  // 4096
#define N0_BLOCKS (NROWS_0/128)  // 2048

// ---------------- scratch (device globals; no allocations allowed) -------------
__device__ float g_qkvb[(size_t)NROWS_B*256];   // q(128)|v(128) of clin(beta)
__device__ float g_qkv0[(size_t)NROWS_0*384];   // clin(mem0): q|k|v
__device__ float g_alpha[NROWS_B];
__device__ float g_ptrs[(size_t)NROWS_B*16];
__device__ float g_betaT[(size_t)BATCH*128];    // beta at t=31 (for mem_f)
__device__ unsigned short g_Wt_hi[384*128];     // W^T split hi (bf16 bits): row n, col d
__device__ unsigned short g_Wt_lo[384*128];
__device__ float g_ropeC[1024], g_ropeS[1024];  // [t][f] rope tables
__device__ int   g_active;

// ---------------- build combined transposed/split weight -----------------------
__global__ void build_wt_kernel(const float* __restrict__ Wqr, const float* __restrict__ Wqi,
                                const float* __restrict__ Wkr, const float* __restrict__ Wki,
                                const float* __restrict__ Wvr, const float* __restrict__ Wvi) {
    int idx = blockIdx.x * blockDim.x + threadIdx.x;
    if (idx >= 384*128) return;
    int n = idx / 128, d = idx % 128;          // n = output col, d = input dim
    int grp = n >> 7, cc = n & 127, e = cc & 63, im = cc >> 6;
    const float* Wr = (grp == 0) ? Wqr : (grp == 1) ? Wkr : Wvr;
    const float* Wi = (grp == 0) ? Wqi : (grp == 1) ? Wki : Wvi;
    int dr = d & 63;
    float v;
    if (im == 0) v = (d < 64) ? Wr[e*64 + dr] : -Wi[e*64 + dr];
    else         v = (d < 64) ? Wi[e*64 + dr] :  Wr[e*64 + dr];
    __nv_bfloat16 h = __float2bfloat16(v);
    float lo = v - __bfloat162float(h);
    __nv_bfloat16 l = __float2bfloat16(lo);
    g_Wt_hi[idx] = __bfloat16_as_ushort(h);
    g_Wt_lo[idx] = __bfloat16_as_ushort(l);
}

__global__ void rope_kernel() {
    int idx = blockIdx.x * blockDim.x + threadIdx.x;
    if (idx >= 1024) return;
    int t = idx >> 5, f = idx & 31;
    double freq = pow(10000.0, -((double)(2*f)) / 64.0);
    float ang = (float)((double)t * freq);
    g_ropeC[idx] = cosf(ang);
    g_ropeS[idx] = sinf(ang);
}

__global__ void reset_kernel() { g_active = 0; }

// ---------------- slim prep: alpha + ptr recurrences (16 lanes / batch) --------
__global__ __launch_bounds__(256) void ptr_alpha_kernel(const float* __restrict__ ctrl,
                                                        const float* __restrict__ ptr0) {
    const int grp = threadIdx.x >> 4;          // 0..15: batch within block
    const int s = threadIdx.x & 15;
    const int b = blockIdx.x*16 + grp;
    float p = ptr0[b*16 + s];
    float alpha = 1.f;
    const float* cb = ctrl + (size_t)b*96;
    for (int t = 0; t < TT; ++t) {
        float c0 = cb[t*3 + 0], c1 = cb[t*3 + 1], c2 = cb[t*3 + 2];
        float g0 = 1.f/(1.f + expf(-c0));
        float g1 = 1.f/(1.f + expf(-c1));
        float g2 = 1.f/(1.f + expf(-c2));
        float tot = g0 + g1 + g2 + 1e-6f;
        float push = g0/tot, pop = g1/tot, stay = g2/tot;
        alpha *= (1.f - push);
        float prev = __shfl_sync(0xffffffffu, p, (s + 15) & 15, 16);
        float nxt  = __shfl_sync(0xffffffffu, p, (s + 1) & 15, 16);
        p = push*prev + pop*nxt + stay*p;
        g_ptrs[((size_t)b*TT + t)*16 + s] = p;
        if (s == 0) g_alpha[b*TT + t] = alpha;
    }
}

// ---------------- HMMA split-bf16 GEMM with fused beta recurrence ---------------
// beta blocks (bid < NB_BLOCKS): 128 rows = 4 batches; A = beta computed inline.
//   2 col-blocks: q (W rows 0..127) and v (W rows 256..383); C stride 256.
// mem0 blocks: A = mem0 rows; 3 col-blocks; C stride 384.
#define ASTRIDE 136            // halves per row (pad 8 -> conflict-free frag loads)
#define SM_AHI 0
#define SM_ALO (128*ASTRIDE*2)       // 34816
#define SM_B   (2*128*ASTRIDE*2)     // 69632
#define SM_TOTAL (3*128*ASTRIDE*2)   // 104448 bytes

__device__ __forceinline__ void mma16816(float* d, const uint32_t* a, const uint32_t* b) {
    asm volatile(
        "mma.sync.aligned.m16n8k16.row.col.f32.bf16.bf16.f32 "
        "{%0,%1,%2,%3},{%4,%5,%6,%7},{%8,%9},{%0,%1,%2,%3};"
        : "+f"(d[0]), "+f"(d[1]), "+f"(d[2]), "+f"(d[3])
        : "r"(a[0]), "r"(a[1]), "r"(a[2]), "r"(a[3]), "r"(b[0]), "r"(b[1]));
}

__global__ __launch_bounds__(256, 2) void gemm_kernel(const float* __restrict__ mem0,
                                                      const float* __restrict__ zr,
                                                      const float* __restrict__ zi,
                                                      const float* __restrict__ ctrl) {
    extern __shared__ char smem[];
    __shared__ float sPush[128];
    unsigned short* sAhi = (unsigned short*)(smem + SM_AHI);
    unsigned short* sAlo = (unsigned short*)(smem + SM_ALO);
    unsigned short* sB   = (unsigned short*)(smem + SM_B);

    const int tid = threadIdx.x;
    const int lane = tid & 31;
    const int wid = tid >> 5;
    const int gid = lane >> 2;       // 0..7
    const int tig = lane & 3;        // 0..3
    const int wr = wid & 3;          // warp row group (4 x 32 rows)
    const int wc = wid >> 2;         // warp col group (2 x 64 cols)

    const bool is_beta = (blockIdx.x < NB_BLOCKS);

    float* C;
    int ncb, cstride;

    if (is_beta) {
        const int b0 = blockIdx.x * 4;     // 4 batches per block
        C = g_qkvb + (size_t)blockIdx.x * 128 * 256;
        ncb = 2; cstride = 256;

        // gates -> sPush[bl*32 + t]
        if (tid < 128) {
            int bl = tid >> 5, t = tid & 31;
            const float* cp = ctrl + ((size_t)(b0 + bl)*TT + t)*3;
            float g0 = 1.f/(1.f + expf(-cp[0]));
            float g1 = 1.f/(1.f + expf(-cp[1]));
            float g2 = 1.f/(1.f + expf(-cp[2]));
            sPush[tid] = g0 / (g0 + g1 + g2 + 1e-6f);
        }
        __syncthreads();

        // beta recurrence: thread = (batch bl, dim dd); handles d=dd and d=dd+64
        {
            const int bl = tid >> 6, dd = tid & 63;
            const float* zrb = zr + (size_t)(b0 + bl)*2048 + dd;
            const float* zib = zi + (size_t)(b0 + bl)*2048 + dd;
            const float* pushp = &sPush[bl*32];
            const int f = dd & 31;
            float bL = 0.f, bH = 0.f;
            #pragma unroll 4
            for (int t = 0; t < TT; ++t) {
                float cs = g_ropeC[t*32 + f];
                float sn = g_ropeS[t*32 + f];
                float a = zrb[t*64], zb = zib[t*64];
                float vL = a*cs - zb*sn;
                float vH = a*sn + zb*cs;
                float push = pushp[t];
                bL = (1.f - push)*bL + push*vL;
                bH = (1.f - push)*bH + push*vH;
                int r = bl*32 + t;
                __nv_bfloat16 h = __float2bfloat16(bL);
                sAhi[r*ASTRIDE + dd] = __bfloat16_as_ushort(h);
                sAlo[r*ASTRIDE + dd] =
                    __bfloat16_as_ushort(__float2bfloat16(bL - __bfloat162float(h)));
                h = __float2bfloat16(bH);
                sAhi[r*ASTRIDE + dd + 64] = __bfloat16_as_ushort(h);
                sAlo[r*ASTRIDE + dd + 64] =
                    __bfloat16_as_ushort(__float2bfloat16(bH - __bfloat162float(h)));
            }
            g_betaT[(size_t)(b0 + bl)*128 + dd] = bL;
            g_betaT[(size_t)(b0 + bl)*128 + dd + 64] = bH;
        }
    } else {
        const size_t row0 = (size_t)(blockIdx.x - NB_BLOCKS) * 128;
        C = g_qkv0 + row0*384;
        ncb = 3; cstride = 384;
        const float* Ab = mem0 + row0*128;
        #pragma unroll
        for (int it = 0; it < 16; ++it) {
            int i = tid + it*256;                 // 0..4095
            int r = i >> 5, k = (i & 31) * 4;
            float4 v = *(const float4*)(Ab + (size_t)r*128 + k);
            __nv_bfloat16 h0 = __float2bfloat16(v.x);
            __nv_bfloat16 h1 = __float2bfloat16(v.y);
            __nv_bfloat16 h2 = __float2bfloat16(v.z);
            __nv_bfloat16 h3 = __float2bfloat16(v.w);
            __nv_bfloat16 l0 = __float2bfloat16(v.x - __bfloat162float(h0));
            __nv_bfloat16 l1 = __float2bfloat16(v.y - __bfloat162float(h1));
            __nv_bfloat16 l2 = __float2bfloat16(v.z - __bfloat162float(h2));
            __nv_bfloat16 l3 = __float2bfloat16(v.w - __bfloat162float(h3));
            uint64_t hv = (uint64_t)__bfloat16_as_ushort(h0)
                        | ((uint64_t)__bfloat16_as_ushort(h1) << 16)
                        | ((uint64_t)__bfloat16_as_ushort(h2) << 32)
                        | ((uint64_t)__bfloat16_as_ushort(h3) << 48);
            uint64_t lv = (uint64_t)__bfloat16_as_ushort(l0)
                        | ((uint64_t)__bfloat16_as_ushort(l1) << 16)
                        | ((uint64_t)__bfloat16_as_ushort(l2) << 32)
                        | ((uint64_t)__bfloat16_as_ushort(l3) << 48);
            *(uint64_t*)&sAhi[r*ASTRIDE + k] = hv;
            *(uint64_t*)&sAlo[r*ASTRIDE + k] = lv;
        }
    }

    for (int cb = 0; cb < ncb; ++cb) {
        const int col0 = cb * 128;
        const int wr0 = is_beta ? (cb == 0 ? 0 : 256) : cb*128;   // W^T row offset

        float acc[2][8][4];
        #pragma unroll
        for (int m = 0; m < 2; ++m)
            #pragma unroll
            for (int j = 0; j < 8; ++j)
                #pragma unroll
                for (int q = 0; q < 4; ++q) acc[m][j][q] = 0.f;

        // -------- phase 1: B = Whi; acc += Ahi@Bhi + Alo@Bhi --------
        __syncthreads();   // A staged / prior compute done; sB free
        #pragma unroll
        for (int it = 0; it < 8; ++it) {
            int i = tid + it*256;
            int r = i >> 4, k = (i & 15) * 8;
            *(uint4*)&sB[r*ASTRIDE + k] = *(const uint4*)(g_Wt_hi + (size_t)(wr0 + r)*128 + k);
        }
        __syncthreads();

        #pragma unroll
        for (int kk = 0; kk < 8; ++kk) {
            const int k0 = kk*16 + 2*tig;
            uint32_t ah[2][4], al[2][4];
            #pragma unroll
            for (int m = 0; m < 2; ++m) {
                int r = wr*32 + m*16 + gid;
                ah[m][0] = *(const uint32_t*)&sAhi[r*ASTRIDE + k0];
                ah[m][1] = *(const uint32_t*)&sAhi[(r+8)*ASTRIDE + k0];
                ah[m][2] = *(const uint32_t*)&sAhi[r*ASTRIDE + k0 + 8];
                ah[m][3] = *(const uint32_t*)&sAhi[(r+8)*ASTRIDE + k0 + 8];
                al[m][0] = *(const uint32_t*)&sAlo[r*ASTRIDE + k0];
                al[m][1] = *(const uint32_t*)&sAlo[(r+8)*ASTRIDE + k0];
                al[m][2] = *(const uint32_t*)&sAlo[r*ASTRIDE + k0 + 8];
                al[m][3] = *(const uint32_t*)&sAlo[(r+8)*ASTRIDE + k0 + 8];
            }
            #pragma unroll
            for (int j = 0; j < 8; ++j) {
                int n = wc*64 + j*8 + gid;
                uint32_t bb[2];
                bb[0] = *(const uint32_t*)&sB[n*ASTRIDE + k0];
                bb[1] = *(const uint32_t*)&sB[n*ASTRIDE + k0 + 8];
                mma16816(acc[0][j], ah[0], bb);
                mma16816(acc[1][j], ah[1], bb);
                mma16816(acc[0][j], al[0], bb);
                mma16816(acc[1][j], al[1], bb);
            }
        }

        // -------- phase 2: B = Wlo; acc += Ahi@Blo --------
        __syncthreads();
        #pragma unroll
        for (int it = 0; it < 8; ++it) {
            int i = tid + it*256;
            int r = i >> 4, k = (i & 15) * 8;
            *(uint4*)&sB[r*ASTRIDE + k] = *(const uint4*)(g_Wt_lo + (size_t)(wr0 + r)*128 + k);
        }
        __syncthreads();

        #pragma unroll
        for (int kk = 0; kk < 8; ++kk) {
            const int k0 = kk*16 + 2*tig;
            uint32_t ah[2][4];
            #pragma unroll
            for (int m = 0; m < 2; ++m) {
                int r = wr*32 + m*16 + gid;
                ah[m][0] = *(const uint32_t*)&sAhi[r*ASTRIDE + k0];
                ah[m][1] = *(const uint32_t*)&sAhi[(r+8)*ASTRIDE + k0];
                ah[m][2] = *(const uint32_t*)&sAhi[r*ASTRIDE + k0 + 8];
                ah[m][3] = *(const uint32_t*)&sAhi[(r+8)*ASTRIDE + k0 + 8];
            }
            #pragma unroll
            for (int j = 0; j < 8; ++j) {
                int n = wc*64 + j*8 + gid;
                uint32_t bb[2];
                bb[0] = *(const uint32_t*)&sB[n*ASTRIDE + k0];
                bb[1] = *(const uint32_t*)&sB[n*ASTRIDE + k0 + 8];
                mma16816(acc[0][j], ah[0], bb);
                mma16816(acc[1][j], ah[1], bb);
            }
        }

        // ---- epilogue: direct gmem stores (local rows) ----
        #pragma unroll
        for (int m = 0; m < 2; ++m) {
            int r = wr*32 + m*16 + gid;
            #pragma unroll
            for (int j = 0; j < 8; ++j) {
                int c = col0 + wc*64 + j*8 + 2*tig;
                *(float2*)(C + (size_t)r*cstride + c)     = make_float2(acc[m][j][0], acc[m][j][1]);
                *(float2*)(C + (size_t)(r+8)*cstride + c) = make_float2(acc[m][j][2], acc[m][j][3]);
            }
        }
    }
}

// ---------------- per-batch scan (t-parallel, 8 t per iteration) ---------------
#define ST 388   // padded slot stride (floats) for sM0

__global__ __launch_bounds__(256) void scan_kernel(const float* __restrict__ mem0,
                                                   float* __restrict__ out) {
    const int b = blockIdx.x;
    const int tid = threadIdx.x;

    __shared__ float sM0[16*ST];       // per-slot: q0f(128)|k0f(128)|v0f(128)
    __shared__ float sG0[16*17];       // G0[s][j], stride 17
    __shared__ float sQ[8*256];        // qkvb (q|v) for 8 t
    __shared__ float sW8[8][16];
    __shared__ float sPA[8*272];       // ptr[s]*attn[s][j], [t][s*17+j]
    __shared__ float sC8[8][16];
    __shared__ float sPtr8[8][16];
    __shared__ float sAl8[8];

    const float* base0 = g_qkv0 + (size_t)b*16*384;
    for (int i = tid; i < 16*384; i += 256)
        sM0[(i/384)*ST + (i % 384)] = base0[i];
    __syncthreads();

    // G0[s][j] = qf0[s] . kf0[j]
    {
        int s = tid >> 4, j = tid & 15;
        const float* q = &sM0[s*ST];
        const float* k = &sM0[j*ST + 128];
        float acc = 0.f;
        #pragma unroll 8
        for (int d = 0; d < 128; ++d) acc += q[d]*k[d];
        sG0[s*17 + j] = acc;
    }

    for (int tc = 0; tc < 4; ++tc) {
        const int t0 = tc*8;
        const size_t bt0 = (size_t)b*TT + t0;

        // stage qkvb / ptr / alpha for 8 t
        {
            const float* bb = g_qkvb + bt0*256;
            for (int i = tid; i < 8*256; i += 256) sQ[i] = bb[i];
            if (tid < 128) {
                int t = tid >> 4, s = tid & 15;
                sPtr8[t][s] = g_ptrs[(bt0 + t)*16 + s];
            }
            if (tid < 8) sAl8[tid] = g_alpha[bt0 + tid];
        }
        __syncthreads();

        // w[t][j] = qbeta(t) . kf0[j]  (2 lanes per dot)
        {
            int t = tid >> 5, jj = tid & 31;
            int j = jj >> 1, half = jj & 1;
            const float* qb = &sQ[t*256];
            const float* kf = &sM0[j*ST + 128];
            int d0 = half*64;
            float acc = 0.f;
            #pragma unroll 8
            for (int d = 0; d < 64; ++d) acc += qb[d0 + d]*kf[d0 + d];
            acc += __shfl_xor_sync(0xffffffffu, acc, 1);
            if (half == 0) sW8[t][j] = acc;
        }
        __syncthreads();

        // softmax per (t,s): logits = 0.125*(a^2*G0[s,j] + a*w[t][j]) (row-consts dropped)
        if (tid < 128) {
            int t = tid >> 4, s = tid & 15;
            float a = sAl8[t], a2 = a*a;
            float L[16], m = -1e30f;
            #pragma unroll
            for (int j = 0; j < 16; ++j) {
                L[j] = 0.125f*(a2*sG0[s*17 + j] + a*sW8[t][j]);
                m = fmaxf(m, L[j]);
            }
            float sum = 0.f;
            #pragma unroll
            for (int j = 0; j < 16; ++j) { L[j] = expf(L[j] - m); sum += L[j]; }
            float pscl = sPtr8[t][s] / sum;
            #pragma unroll
            for (int j = 0; j < 16; ++j) sPA[t*272 + s*17 + j] = pscl*L[j];
        }
        __syncthreads();

        // c[t][j] = sum_s ptr[s]*attn[s][j]
        if (tid < 128) {
            int t = tid >> 4, j = tid & 15;
            float c = 0.f;
            #pragma unroll
            for (int s = 0; s < 16; ++s) c += sPA[t*272 + s*17 + j];
            sC8[t][j] = c;
        }
        __syncthreads();

        // read[t][d] = a * sum_j c[j]*v0f[j][d] + csum * vbeta[d]
        {
            int t = tid >> 5, lane2 = tid & 31;
            float a = sAl8[t];
            float cj[16], csum = 0.f;
            #pragma unroll
            for (int j = 0; j < 16; ++j) { cj[j] = sC8[t][j]; csum += cj[j]; }
            float* ob = out + ((size_t)(t0 + t)*BATCH + b)*128;
            #pragma unroll
            for (int dd = 0; dd < 4; ++dd) {
                int d = lane2 + dd*32;
                float r = 0.f;
                #pragma unroll
                for (int j = 0; j < 16; ++j) r += cj[j]*sM0[j*ST + 256 + d];
                ob[d] = a*r + csum*sQ[t*256 + 128 + d];
            }
        }
        __syncthreads();
    }

    // epilogue: mem_f = alpha_T*mem0 + beta_T ; ptr_f ; active count
    const float alphaT = g_alpha[(size_t)b*TT + (TT - 1)];
    if (tid < 128) sQ[tid] = g_betaT[(size_t)b*128 + tid];
    __syncthreads();

    float* out_mem = out + (size_t)TT*BATCH*128;
    const float* m0 = mem0 + (size_t)b*2048;
    for (int i = tid; i < 2048; i += 256)
        out_mem[(size_t)b*2048 + i] = alphaT*m0[i] + sQ[i & 127];

    float* out_ptr = out + (size_t)TT*BATCH*128 + (size_t)BATCH*2048;
    if (tid < 16) {
        float pv = g_ptrs[((size_t)b*TT + (TT - 1))*16 + tid];
        out_ptr[(size_t)b*16 + tid] = pv;
        int cnt = (pv > 0.1f) ? 1 : 0;
        cnt += __shfl_xor_sync(0x0000ffffu, cnt, 8, 16);
        cnt += __shfl_xor_sync(0x0000ffffu, cnt, 4, 16);
        cnt += __shfl_xor_sync(0x0000ffffu, cnt, 2, 16);
        cnt += __shfl_xor_sync(0x0000ffffu, cnt, 1, 16);
        if (tid == 0) atomicAdd(&g_active, cnt);
    }
}

__global__ void finalize_kernel(float* __restrict__ out) {
    out[(size_t)TT*BATCH*128 + (size_t)BATCH*2048 + (size_t)BATCH*16] =
        (float)g_active / (float)BATCH;
}

// ---------------- launcher ----------------------------------------------------
extern "C" void kernel_launch(void* const* d_in, const int* in_sizes, int n_in,
                              void* d_out, int out_size) {
    const float* zr   = (const float*)d_in[0];
    const float* zi   = (const float*)d_in[1];
    const float* ctrl = (const float*)d_in[2];
    const float* mem0 = (const float*)d_in[3];
    const float* ptr0 = (const float*)d_in[4];
    const float* Wqr  = (const float*)d_in[5];
    const float* Wqi  = (const float*)d_in[6];
    const float* Wkr  = (const float*)d_in[7];
    const float* Wki  = (const float*)d_in[8];
    const float* Wvr  = (const float*)d_in[9];
    const float* Wvi  = (const float*)d_in[10];
    float* out = (float*)d_out;

    cudaFuncSetAttribute(gemm_kernel, cudaFuncAttributeMaxDynamicSharedMemorySize, SM_TOTAL);

    build_wt_kernel<<<192, 256>>>(Wqr, Wqi, Wkr, Wki, Wvr, Wvi);
    rope_kernel<<<4, 256>>>();
    reset_kernel<<<1, 1>>>();
    ptr_alpha_kernel<<<BATCH/16, 256>>>(ctrl, ptr0);

    gemm_kernel<<<NB_BLOCKS + N0_BLOCKS, 256, SM_TOTAL>>>(mem0, zr, zi, ctrl);

    scan_kernel<<<BATCH, 256>>>(mem0, out);
    finalize_kernel<<<1, 1>>>(out);
}

// round 8
// speedup vs baseline: 3.4129x; 1.1155x over previous
#include <cuda_runtime.h>
#include <cuda_bf16.h>
#include <math.h>
#include <stdint.h>

#define BATCH 16384
#define TT 32
#define SS 16
#define NROWS_B (BATCH*TT)   // 524288
#define NROWS_0 (BATCH*SS)   // 262144
#define NB_BLOCKS (NROWS_B/128)  // 4096
#define N0_BLOCKS (NROWS_0/128)  // 2048

// ---------------- scratch (device globals; no allocations allowed) -------------
__device__ float g_qkvb[(size_t)NROWS_B*256];   // q(128)|v(128) of clin(beta)
__device__ float g_qkv0[(size_t)NROWS_0*384];   // clin(mem0): q|k|v
__device__ float g_alpha[NROWS_B];
__device__ float g_ptrs[(size_t)NROWS_B*16];
__device__ float g_betaT[(size_t)BATCH*128];    // beta at t=31 (for mem_f)
__device__ unsigned short g_Wt_hi[384*128];     // W^T split hi (bf16 bits): row n, col d
__device__ unsigned short g_Wt_lo[384*128];
__device__ float g_ropeC[1024], g_ropeS[1024];  // [t][f] rope tables
__device__ int   g_active;

// ---------------- build combined transposed/split weight -----------------------
__global__ void build_wt_kernel(const float* __restrict__ Wqr, const float* __restrict__ Wqi,
                                const float* __restrict__ Wkr, const float* __restrict__ Wki,
                                const float* __restrict__ Wvr, const float* __restrict__ Wvi) {
    int idx = blockIdx.x * blockDim.x + threadIdx.x;
    if (idx >= 384*128) return;
    int n = idx / 128, d = idx % 128;          // n = output col, d = input dim
    int grp = n >> 7, cc = n & 127, e = cc & 63, im = cc >> 6;
    const float* Wr = (grp == 0) ? Wqr : (grp == 1) ? Wkr : Wvr;
    const float* Wi = (grp == 0) ? Wqi : (grp == 1) ? Wki : Wvi;
    int dr = d & 63;
    float v;
    if (im == 0) v = (d < 64) ? Wr[e*64 + dr] : -Wi[e*64 + dr];
    else         v = (d < 64) ? Wi[e*64 + dr] :  Wr[e*64 + dr];
    __nv_bfloat16 h = __float2bfloat16(v);
    float lo = v - __bfloat162float(h);
    __nv_bfloat16 l = __float2bfloat16(lo);
    g_Wt_hi[idx] = __bfloat16_as_ushort(h);
    g_Wt_lo[idx] = __bfloat16_as_ushort(l);
}

__global__ void rope_kernel() {
    int idx = blockIdx.x * blockDim.x + threadIdx.x;
    if (idx >= 1024) return;
    int t = idx >> 5, f = idx & 31;
    double freq = pow(10000.0, -((double)(2*f)) / 64.0);
    float ang = (float)((double)t * freq);
    g_ropeC[idx] = cosf(ang);
    g_ropeS[idx] = sinf(ang);
}

__global__ void reset_kernel() { g_active = 0; }

// ---------------- slim prep: alpha + ptr recurrences (16 lanes / batch) --------
__global__ __launch_bounds__(256) void ptr_alpha_kernel(const float* __restrict__ ctrl,
                                                        const float* __restrict__ ptr0) {
    const int grp = threadIdx.x >> 4;          // 0..15: batch within block
    const int s = threadIdx.x & 15;
    const int b = blockIdx.x*16 + grp;
    float p = ptr0[b*16 + s];
    float alpha = 1.f;
    const float* cb = ctrl + (size_t)b*96;
    for (int t = 0; t < TT; ++t) {
        float c0 = cb[t*3 + 0], c1 = cb[t*3 + 1], c2 = cb[t*3 + 2];
        float g0 = 1.f/(1.f + expf(-c0));
        float g1 = 1.f/(1.f + expf(-c1));
        float g2 = 1.f/(1.f + expf(-c2));
        float tot = g0 + g1 + g2 + 1e-6f;
        float push = g0/tot, pop = g1/tot, stay = g2/tot;
        alpha *= (1.f - push);
        float prev = __shfl_sync(0xffffffffu, p, (s + 15) & 15, 16);
        float nxt  = __shfl_sync(0xffffffffu, p, (s + 1) & 15, 16);
        p = push*prev + pop*nxt + stay*p;
        g_ptrs[((size_t)b*TT + t)*16 + s] = p;
        if (s == 0) g_alpha[b*TT + t] = alpha;
    }
}

// ---------------- HMMA split-bf16 GEMM with fused beta recurrence ---------------
#define ASTRIDE 136            // halves per row (pad 8 -> conflict-free frag loads)
#define SM_AHI 0
#define SM_ALO (128*ASTRIDE*2)       // 34816
#define SM_B   (2*128*ASTRIDE*2)     // 69632
#define SM_TOTAL (3*128*ASTRIDE*2)   // 104448 bytes

__device__ __forceinline__ void mma16816(float* d, const uint32_t* a, const uint32_t* b) {
    asm volatile(
        "mma.sync.aligned.m16n8k16.row.col.f32.bf16.bf16.f32 "
        "{%0,%1,%2,%3},{%4,%5,%6,%7},{%8,%9},{%0,%1,%2,%3};"
        : "+f"(d[0]), "+f"(d[1]), "+f"(d[2]), "+f"(d[3])
        : "r"(a[0]), "r"(a[1]), "r"(a[2]), "r"(a[3]), "r"(b[0]), "r"(b[1]));
}

__global__ __launch_bounds__(256, 2) void gemm_kernel(const float* __restrict__ mem0,
                                                      const float* __restrict__ zr,
                                                      const float* __restrict__ zi,
                                                      const float* __restrict__ ctrl) {
    extern __shared__ char smem[];
    __shared__ float sPush[128];
    unsigned short* sAhi = (unsigned short*)(smem + SM_AHI);
    unsigned short* sAlo = (unsigned short*)(smem + SM_ALO);
    unsigned short* sB   = (unsigned short*)(smem + SM_B);

    const int tid = threadIdx.x;
    const int lane = tid & 31;
    const int wid = tid >> 5;
    const int gid = lane >> 2;       // 0..7
    const int tig = lane & 3;        // 0..3
    const int wr = wid & 3;          // warp row group (4 x 32 rows)
    const int wc = wid >> 2;         // warp col group (2 x 64 cols)

    const bool is_beta = (blockIdx.x < NB_BLOCKS);

    float* C;
    int ncb, cstride;

    if (is_beta) {
        const int b0 = blockIdx.x * 4;     // 4 batches per block
        C = g_qkvb + (size_t)blockIdx.x * 128 * 256;
        ncb = 2; cstride = 256;

        if (tid < 128) {
            int bl = tid >> 5, t = tid & 31;
            const float* cp = ctrl + ((size_t)(b0 + bl)*TT + t)*3;
            float g0 = 1.f/(1.f + expf(-cp[0]));
            float g1 = 1.f/(1.f + expf(-cp[1]));
            float g2 = 1.f/(1.f + expf(-cp[2]));
            sPush[tid] = g0 / (g0 + g1 + g2 + 1e-6f);
        }
        __syncthreads();

        {
            const int bl = tid >> 6, dd = tid & 63;
            const float* zrb = zr + (size_t)(b0 + bl)*2048 + dd;
            const float* zib = zi + (size_t)(b0 + bl)*2048 + dd;
            const float* pushp = &sPush[bl*32];
            const int f = dd & 31;
            float bL = 0.f, bH = 0.f;
            #pragma unroll 4
            for (int t = 0; t < TT; ++t) {
                float cs = g_ropeC[t*32 + f];
                float sn = g_ropeS[t*32 + f];
                float a = zrb[t*64], zb = zib[t*64];
                float vL = a*cs - zb*sn;
                float vH = a*sn + zb*cs;
                float push = pushp[t];
                bL = (1.f - push)*bL + push*vL;
                bH = (1.f - push)*bH + push*vH;
                int r = bl*32 + t;
                __nv_bfloat16 h = __float2bfloat16(bL);
                sAhi[r*ASTRIDE + dd] = __bfloat16_as_ushort(h);
                sAlo[r*ASTRIDE + dd] =
                    __bfloat16_as_ushort(__float2bfloat16(bL - __bfloat162float(h)));
                h = __float2bfloat16(bH);
                sAhi[r*ASTRIDE + dd + 64] = __bfloat16_as_ushort(h);
                sAlo[r*ASTRIDE + dd + 64] =
                    __bfloat16_as_ushort(__float2bfloat16(bH - __bfloat162float(h)));
            }
            g_betaT[(size_t)(b0 + bl)*128 + dd] = bL;
            g_betaT[(size_t)(b0 + bl)*128 + dd + 64] = bH;
        }
    } else {
        const size_t row0 = (size_t)(blockIdx.x - NB_BLOCKS) * 128;
        C = g_qkv0 + row0*384;
        ncb = 3; cstride = 384;
        const float* Ab = mem0 + row0*128;
        #pragma unroll
        for (int it = 0; it < 16; ++it) {
            int i = tid + it*256;                 // 0..4095
            int r = i >> 5, k = (i & 31) * 4;
            float4 v = *(const float4*)(Ab + (size_t)r*128 + k);
            __nv_bfloat16 h0 = __float2bfloat16(v.x);
            __nv_bfloat16 h1 = __float2bfloat16(v.y);
            __nv_bfloat16 h2 = __float2bfloat16(v.z);
            __nv_bfloat16 h3 = __float2bfloat16(v.w);
            __nv_bfloat16 l0 = __float2bfloat16(v.x - __bfloat162float(h0));
            __nv_bfloat16 l1 = __float2bfloat16(v.y - __bfloat162float(h1));
            __nv_bfloat16 l2 = __float2bfloat16(v.z - __bfloat162float(h2));
            __nv_bfloat16 l3 = __float2bfloat16(v.w - __bfloat162float(h3));
            uint64_t hv = (uint64_t)__bfloat16_as_ushort(h0)
                        | ((uint64_t)__bfloat16_as_ushort(h1) << 16)
                        | ((uint64_t)__bfloat16_as_ushort(h2) << 32)
                        | ((uint64_t)__bfloat16_as_ushort(h3) << 48);
            uint64_t lv = (uint64_t)__bfloat16_as_ushort(l0)
                        | ((uint64_t)__bfloat16_as_ushort(l1) << 16)
                        | ((uint64_t)__bfloat16_as_ushort(l2) << 32)
                        | ((uint64_t)__bfloat16_as_ushort(l3) << 48);
            *(uint64_t*)&sAhi[r*ASTRIDE + k] = hv;
            *(uint64_t*)&sAlo[r*ASTRIDE + k] = lv;
        }
    }

    for (int cb = 0; cb < ncb; ++cb) {
        const int col0 = cb * 128;
        const int wr0 = is_beta ? (cb == 0 ? 0 : 256) : cb*128;   // W^T row offset

        float acc[2][8][4];
        #pragma unroll
        for (int m = 0; m < 2; ++m)
            #pragma unroll
            for (int j = 0; j < 8; ++j)
                #pragma unroll
                for (int q = 0; q < 4; ++q) acc[m][j][q] = 0.f;

        // -------- phase 1: B = Whi; acc += Ahi@Bhi + Alo@Bhi --------
        __syncthreads();
        #pragma unroll
        for (int it = 0; it < 8; ++it) {
            int i = tid + it*256;
            int r = i >> 4, k = (i & 15) * 8;
            *(uint4*)&sB[r*ASTRIDE + k] = *(const uint4*)(g_Wt_hi + (size_t)(wr0 + r)*128 + k);
        }
        __syncthreads();

        #pragma unroll
        for (int kk = 0; kk < 8; ++kk) {
            const int k0 = kk*16 + 2*tig;
            uint32_t ah[2][4], al[2][4];
            #pragma unroll
            for (int m = 0; m < 2; ++m) {
                int r = wr*32 + m*16 + gid;
                ah[m][0] = *(const uint32_t*)&sAhi[r*ASTRIDE + k0];
                ah[m][1] = *(const uint32_t*)&sAhi[(r+8)*ASTRIDE + k0];
                ah[m][2] = *(const uint32_t*)&sAhi[r*ASTRIDE + k0 + 8];
                ah[m][3] = *(const uint32_t*)&sAhi[(r+8)*ASTRIDE + k0 + 8];
                al[m][0] = *(const uint32_t*)&sAlo[r*ASTRIDE + k0];
                al[m][1] = *(const uint32_t*)&sAlo[(r+8)*ASTRIDE + k0];
                al[m][2] = *(const uint32_t*)&sAlo[r*ASTRIDE + k0 + 8];
                al[m][3] = *(const uint32_t*)&sAlo[(r+8)*ASTRIDE + k0 + 8];
            }
            #pragma unroll
            for (int j = 0; j < 8; ++j) {
                int n = wc*64 + j*8 + gid;
                uint32_t bb[2];
                bb[0] = *(const uint32_t*)&sB[n*ASTRIDE + k0];
                bb[1] = *(const uint32_t*)&sB[n*ASTRIDE + k0 + 8];
                mma16816(acc[0][j], ah[0], bb);
                mma16816(acc[1][j], ah[1], bb);
                mma16816(acc[0][j], al[0], bb);
                mma16816(acc[1][j], al[1], bb);
            }
        }

        // -------- phase 2: B = Wlo; acc += Ahi@Blo --------
        __syncthreads();
        #pragma unroll
        for (int it = 0; it < 8; ++it) {
            int i = tid + it*256;
            int r = i >> 4, k = (i & 15) * 8;
            *(uint4*)&sB[r*ASTRIDE + k] = *(const uint4*)(g_Wt_lo + (size_t)(wr0 + r)*128 + k);
        }
        __syncthreads();

        #pragma unroll
        for (int kk = 0; kk < 8; ++kk) {
            const int k0 = kk*16 + 2*tig;
            uint32_t ah[2][4];
            #pragma unroll
            for (int m = 0; m < 2; ++m) {
                int r = wr*32 + m*16 + gid;
                ah[m][0] = *(const uint32_t*)&sAhi[r*ASTRIDE + k0];
                ah[m][1] = *(const uint32_t*)&sAhi[(r+8)*ASTRIDE + k0];
                ah[m][2] = *(const uint32_t*)&sAhi[r*ASTRIDE + k0 + 8];
                ah[m][3] = *(const uint32_t*)&sAhi[(r+8)*ASTRIDE + k0 + 8];
            }
            #pragma unroll
            for (int j = 0; j < 8; ++j) {
                int n = wc*64 + j*8 + gid;
                uint32_t bb[2];
                bb[0] = *(const uint32_t*)&sB[n*ASTRIDE + k0];
                bb[1] = *(const uint32_t*)&sB[n*ASTRIDE + k0 + 8];
                mma16816(acc[0][j], ah[0], bb);
                mma16816(acc[1][j], ah[1], bb);
            }
        }

        // ---- epilogue: direct gmem stores (local rows) ----
        #pragma unroll
        for (int m = 0; m < 2; ++m) {
            int r = wr*32 + m*16 + gid;
            #pragma unroll
            for (int j = 0; j < 8; ++j) {
                int c = col0 + wc*64 + j*8 + 2*tig;
                *(float2*)(C + (size_t)r*cstride + c)     = make_float2(acc[m][j][0], acc[m][j][1]);
                *(float2*)(C + (size_t)(r+8)*cstride + c) = make_float2(acc[m][j][2], acc[m][j][3]);
            }
        }
    }
}

// ---------------- per-batch scan: warp-autonomous, 4 t per warp ----------------
#define ST 388   // padded slot stride (floats) for sM0

__global__ __launch_bounds__(256) void scan_kernel(const float* __restrict__ mem0,
                                                   float* __restrict__ out) {
    const int b = blockIdx.x;
    const int tid = threadIdx.x;
    const int wid = tid >> 5;
    const int lane = tid & 31;

    __shared__ __align__(16) float sM0[16*ST];   // per-slot: q0f|k0f|v0f
    __shared__ float sG0[16*17];                 // G0[s][j]
    __shared__ float sPA[8][16*17];              // per-warp ptr*attn tile
    __shared__ float sPtrAll[512];               // ptr for all 32 t
    __shared__ float sAlphaAll[32];

    const float* base0 = g_qkv0 + (size_t)b*6144;
    for (int i = tid; i < 6144; i += 256)
        sM0[(i/384)*ST + (i % 384)] = base0[i];
    {
        const float* pb = g_ptrs + (size_t)b*512;
        for (int i = tid; i < 512; i += 256) sPtrAll[i] = pb[i];
        if (tid < 32) sAlphaAll[tid] = g_alpha[(size_t)b*32 + tid];
    }
    __syncthreads();

    // G0[s][j] = qf0[s] . kf0[j]
    {
        int s = tid >> 4, j = tid & 15;
        const float* q = &sM0[s*ST];
        const float* k = &sM0[j*ST + 128];
        float acc = 0.f;
        #pragma unroll 8
        for (int d = 0; d < 128; ++d) acc += q[d]*k[d];
        sG0[s*17 + j] = acc;
    }
    __syncthreads();

    const int s = lane >> 1, h = lane & 1;
    float* paw = sPA[wid];

    for (int it = 0; it < 4; ++it) {
        const int t = wid + it*8;
        const float* bb = g_qkvb + ((size_t)b*TT + t)*256;
        const float4 q4 = *(const float4*)(bb + lane*4);
        const float4 v4b = *(const float4*)(bb + 128 + lane*4);

        // w[j] = qbeta . kf0[j] — butterfly; result on ALL lanes
        float wreg[16];
        #pragma unroll
        for (int j = 0; j < 16; ++j) {
            const float4 k4 = *(const float4*)&sM0[j*ST + 128 + lane*4];
            float p = q4.x*k4.x + q4.y*k4.y + q4.z*k4.z + q4.w*k4.w;
            p += __shfl_xor_sync(0xffffffffu, p, 16);
            p += __shfl_xor_sync(0xffffffffu, p, 8);
            p += __shfl_xor_sync(0xffffffffu, p, 4);
            p += __shfl_xor_sync(0xffffffffu, p, 2);
            p += __shfl_xor_sync(0xffffffffu, p, 1);
            wreg[j] = p;
        }

        const float a = sAlphaAll[t];
        const float a2 = a*a;
        const float ptr_s = sPtrAll[t*16 + s];

        // softmax row s (2 lanes: 8 j each); row-constant terms dropped (exact)
        float L[8], m = -1e30f;
        #pragma unroll
        for (int i = 0; i < 8; ++i) {
            int j = h*8 + i;
            L[i] = 0.125f*(a2*sG0[s*17 + j] + a*wreg[j]);
            m = fmaxf(m, L[i]);
        }
        m = fmaxf(m, __shfl_xor_sync(0xffffffffu, m, 1));
        float sum = 0.f;
        #pragma unroll
        for (int i = 0; i < 8; ++i) { L[i] = expf(L[i] - m); sum += L[i]; }
        sum += __shfl_xor_sync(0xffffffffu, sum, 1);
        const float pscl = ptr_s / sum;
        #pragma unroll
        for (int i = 0; i < 8; ++i) paw[s*17 + h*8 + i] = pscl*L[i];
        __syncwarp();

        // c[j] = sum_s pa[s][j]  (2 lanes per j: 8 s each)
        float cacc = 0.f;
        {
            int jc = lane >> 1, s0 = (lane & 1)*8;
            #pragma unroll
            for (int ss = 0; ss < 8; ++ss) cacc += paw[(s0 + ss)*17 + jc];
            cacc += __shfl_xor_sync(0xffffffffu, cacc, 1);
        }
        __syncwarp();   // pa consumed before next iteration overwrites

        // read[d] = a * sum_j c[j]*v0f[j][d] + csum * vbeta[d]
        float4 r = make_float4(0.f, 0.f, 0.f, 0.f);
        float csum = 0.f;
        #pragma unroll
        for (int j = 0; j < 16; ++j) {
            float cj = __shfl_sync(0xffffffffu, cacc, j << 1);
            const float4 vv = *(const float4*)&sM0[j*ST + 256 + lane*4];
            r.x += cj*vv.x; r.y += cj*vv.y; r.z += cj*vv.z; r.w += cj*vv.w;
            csum += cj;
        }
        float4 o;
        o.x = a*r.x + csum*v4b.x;
        o.y = a*r.y + csum*v4b.y;
        o.z = a*r.z + csum*v4b.z;
        o.w = a*r.w + csum*v4b.w;
        *(float4*)(out + ((size_t)t*BATCH + b)*128 + lane*4) = o;
    }

    // epilogue: mem_f = alpha_T*mem0 + beta_T ; ptr_f ; active count
    __syncthreads();
    if (tid < 128) sG0[tid] = g_betaT[(size_t)b*128 + tid];
    __syncthreads();

    const float alphaT = sAlphaAll[31];
    float* out_mem = out + (size_t)TT*BATCH*128;
    const float* m0 = mem0 + (size_t)b*2048;
    for (int i = tid; i < 2048; i += 256)
        out_mem[(size_t)b*2048 + i] = alphaT*m0[i] + sG0[i & 127];

    float* out_ptr = out + (size_t)TT*BATCH*128 + (size_t)BATCH*2048;
    if (tid < 16) {
        float pv = sPtrAll[31*16 + tid];
        out_ptr[(size_t)b*16 + tid] = pv;
        int cnt = (pv > 0.1f) ? 1 : 0;
        cnt += __shfl_xor_sync(0x0000ffffu, cnt, 8, 16);
        cnt += __shfl_xor_sync(0x0000ffffu, cnt, 4, 16);
        cnt += __shfl_xor_sync(0x0000ffffu, cnt, 2, 16);
        cnt += __shfl_xor_sync(0x0000ffffu, cnt, 1, 16);
        if (tid == 0) atomicAdd(&g_active, cnt);
    }
}

__global__ void finalize_kernel(float* __restrict__ out) {
    out[(size_t)TT*BATCH*128 + (size_t)BATCH*2048 + (size_t)BATCH*16] =
        (float)g_active / (float)BATCH;
}

// ---------------- launcher ----------------------------------------------------
extern "C" void kernel_launch(void* const* d_in, const int* in_sizes, int n_in,
                              void* d_out, int out_size) {
    const float* zr   = (const float*)d_in[0];
    const float* zi   = (const float*)d_in[1];
    const float* ctrl = (const float*)d_in[2];
    const float* mem0 = (const float*)d_in[3];
    const float* ptr0 = (const float*)d_in[4];
    const float* Wqr  = (const float*)d_in[5];
    const float* Wqi  = (const float*)d_in[6];
    const float* Wkr  = (const float*)d_in[7];
    const float* Wki  = (const float*)d_in[8];
    const float* Wvr  = (const float*)d_in[9];
    const float* Wvi  = (const float*)d_in[10];
    float* out = (float*)d_out;

    cudaFuncSetAttribute(gemm_kernel, cudaFuncAttributeMaxDynamicSharedMemorySize, SM_TOTAL);

    build_wt_kernel<<<192, 256>>>(Wqr, Wqi, Wkr, Wki, Wvr, Wvi);
    rope_kernel<<<4, 256>>>();
    reset_kernel<<<1, 1>>>();
    ptr_alpha_kernel<<<BATCH/16, 256>>>(ctrl, ptr0);

    gemm_kernel<<<NB_BLOCKS + N0_BLOCKS, 256, SM_TOTAL>>>(mem0, zr, zi, ctrl);

    scan_kernel<<<BATCH, 256>>>(mem0, out);
    finalize_kernel<<<1, 1>>>(out);
}